// round 7
// baseline (speedup 1.0000x reference)
#include <cuda_runtime.h>
#include <cuda_bf16.h>
#include <cuda_fp16.h>
#include <cstdint>
#include <cstddef>

#define B_   64
#define S_   256
#define D_   512
#define H_   1024
#define G4_  4096
#define NCTA 128
#define RSTR 66   // Rbuf row stride in floats (264B, multiple of 8B)

// ---------------- scratch (device globals) ----------------
__device__ __align__(128) float g_gx[67108864];            // [S][4H][B]
__device__ __align__(128) float g_h1[16777216];            // [S][H][B]
__device__ __align__(128) float g_h2[16777216];            // [S][H][B]
__device__ __align__(128) unsigned char g_WF[33554432];    // A fragments: [l][cta][w][mt][kt][lane][hi uint4|lo uint4] (fp16)
__device__ __align__(128) unsigned char g_hfrag[262144];   // [buf][ktile 64][ntile 8][lane 32] uint2 {b0,b1} fp16
__device__ int g_flags[256];

// ---------------- helpers ----------------
__device__ __forceinline__ unsigned long long pk2(float x, float y) {
    unsigned long long r; asm("mov.b64 %0, {%1, %2};" : "=l"(r) : "f"(x), "f"(y)); return r;
}
__device__ __forceinline__ float2 upk2(unsigned long long v) {
    float2 r; asm("mov.b64 {%0, %1}, %2;" : "=f"(r.x), "=f"(r.y) : "l"(v)); return r;
}
__device__ __forceinline__ void fma2(unsigned long long& d, unsigned long long a, unsigned long long b) {
    asm("fma.rn.f32x2 %0, %1, %2, %0;" : "+l"(d) : "l"(a), "l"(b));
}
__device__ __forceinline__ float sigf(float x)   { return 1.f / (1.f + __expf(-x)); }
__device__ __forceinline__ float tanhf_(float x) { return 2.f / (1.f + __expf(-2.f * x)) - 1.f; }
__device__ __forceinline__ float actf(float x)   { return x > 0.f ? 1.f / (1.f + __expf(-x)) : 0.5f; }

__device__ __forceinline__ unsigned short f16of(float v) {
    __half h = __float2half(v);
    return *(unsigned short*)&h;
}
__device__ __forceinline__ float f16val(unsigned short u) {
    __half h = *(__half*)&u;
    return __half2float(h);
}

__device__ __forceinline__ void mma16816(float* d, const unsigned* a, unsigned b0, unsigned b1) {
    asm volatile("mma.sync.aligned.m16n8k16.row.col.f32.f16.f16.f32 "
                 "{%0,%1,%2,%3}, {%4,%5,%6,%7}, {%8,%9}, {%0,%1,%2,%3};"
                 : "+f"(d[0]), "+f"(d[1]), "+f"(d[2]), "+f"(d[3])
                 : "r"(a[0]), "r"(a[1]), "r"(a[2]), "r"(a[3]), "r"(b0), "r"(b1));
}

// ---------------- input GEMM (FFMA2) ----------------
template<int KDIM, int MODEB>
__global__ void __launch_bounds__(256)
gemm_gx_kernel(const float* __restrict__ W, const float* __restrict__ X,
               const float* __restrict__ bA, const float* __restrict__ bB,
               float* __restrict__ gx)
{
    __shared__ float As[16][132];
    __shared__ float Bs[16][68];
    const int s  = blockIdx.y, gt = blockIdx.x, t = threadIdx.x;
    const int tx = t & 15, ty = t >> 4;
    const int b0 = tx * 4, g0 = ty * 8;
    unsigned long long acc[8][2];
#pragma unroll
    for (int i = 0; i < 8; ++i) { acc[i][0] = 0ull; acc[i][1] = 0ull; }
    const int rA = t >> 1, cA = (t & 1) * 8;

    for (int kt = 0; kt < KDIM / 16; ++kt) {
        {
            const float* src = W + (size_t)(gt * 128 + rA) * KDIM + kt * 16 + cA;
            float4 a0 = *(const float4*)src;
            float4 a1 = *(const float4*)(src + 4);
            As[cA + 0][rA] = a0.x; As[cA + 1][rA] = a0.y; As[cA + 2][rA] = a0.z; As[cA + 3][rA] = a0.w;
            As[cA + 4][rA] = a1.x; As[cA + 5][rA] = a1.y; As[cA + 6][rA] = a1.z; As[cA + 7][rA] = a1.w;
        }
        if (MODEB == 0) {
            int bb = t >> 2, q = (t & 3) * 4;
            float4 v = *(const float4*)(X + ((size_t)bb * S_ + s) * KDIM + kt * 16 + q);
            Bs[q + 0][bb] = v.x; Bs[q + 1][bb] = v.y; Bs[q + 2][bb] = v.z; Bs[q + 3][bb] = v.w;
        } else {
            int dk = t >> 4, bb = (t & 15) * 4;
            float4 v = *(const float4*)(X + ((size_t)s * KDIM + kt * 16 + dk) * B_ + bb);
            *(float4*)&Bs[dk][bb] = v;
        }
        __syncthreads();
#pragma unroll
        for (int k = 0; k < 16; ++k) {
            float4 a0 = *(const float4*)&As[k][g0];
            float4 a1 = *(const float4*)&As[k][g0 + 4];
            float4 bv = *(const float4*)&Bs[k][b0];
            unsigned long long bp0 = pk2(bv.x, bv.y), bp1 = pk2(bv.z, bv.w), av;
            av = pk2(a0.x, a0.x); fma2(acc[0][0], av, bp0); fma2(acc[0][1], av, bp1);
            av = pk2(a0.y, a0.y); fma2(acc[1][0], av, bp0); fma2(acc[1][1], av, bp1);
            av = pk2(a0.z, a0.z); fma2(acc[2][0], av, bp0); fma2(acc[2][1], av, bp1);
            av = pk2(a0.w, a0.w); fma2(acc[3][0], av, bp0); fma2(acc[3][1], av, bp1);
            av = pk2(a1.x, a1.x); fma2(acc[4][0], av, bp0); fma2(acc[4][1], av, bp1);
            av = pk2(a1.y, a1.y); fma2(acc[5][0], av, bp0); fma2(acc[5][1], av, bp1);
            av = pk2(a1.z, a1.z); fma2(acc[6][0], av, bp0); fma2(acc[6][1], av, bp1);
            av = pk2(a1.w, a1.w); fma2(acc[7][0], av, bp0); fma2(acc[7][1], av, bp1);
        }
        __syncthreads();
    }
#pragma unroll
    for (int gi = 0; gi < 8; ++gi) {
        int g = gt * 128 + g0 + gi;
        float bias = bA[g] + bB[g];
        float2 p0 = upk2(acc[gi][0]), p1 = upk2(acc[gi][1]);
        *(float4*)(gx + ((size_t)s * G4_ + g) * B_ + b0) =
            make_float4(p0.x + bias, p0.y + bias, p1.x + bias, p1.y + bias);
    }
}

// ---------------- weight prep: Whh -> per-thread mma A fragments (fp16 hi/lo split) ----------------
__global__ void __launch_bounds__(256)
prep_w_kernel(const float* __restrict__ Whh0, const float* __restrict__ Whh1)
{
    unsigned idx  = blockIdx.x * 256 + threadIdx.x;   // 2^20
    unsigned lane = idx & 31;
    unsigned kt   = (idx >> 5) & 7;
    unsigned mt   = (idx >> 8) & 1;
    unsigned w    = (idx >> 9) & 7;
    unsigned cta  = (idx >> 12) & 127;
    unsigned l    = idx >> 19;
    const float* W = l ? Whh1 : Whh0;

    unsigned hi[4], lo[4];
#pragma unroll
    for (int p = 0; p < 4; ++p) {
        unsigned r = (lane >> 2) + (p & 1) * 8;
        unsigned c = (lane & 3) * 2 + (p >> 1) * 8;
        unsigned rloc = mt * 16 + r;
        unsigned gr = cta * 32 + rloc;
        unsigned j = gr >> 2, gate = gr & 3;
        unsigned k = w * 128 + kt * 16 + c;
        float2 v = *(const float2*)(W + ((size_t)(gate * H_ + j)) * H_ + k);
        unsigned short h0 = f16of(v.x);
        unsigned short l0 = f16of(v.x - f16val(h0));
        unsigned short h1 = f16of(v.y);
        unsigned short l1 = f16of(v.y - f16val(h1));
        hi[p] = (unsigned)h0 | ((unsigned)h1 << 16);
        lo[p] = (unsigned)l0 | ((unsigned)l1 << 16);
    }
    size_t fr = ((((size_t)(l * 128 + cta) * 8 + w) * 2 + mt) * 8 + kt) * 32 + lane;
    uint4* dst = (uint4*)g_WF + fr * 2;
    dst[0] = make_uint4(hi[0], hi[1], hi[2], hi[3]);
    dst[1] = make_uint4(lo[0], lo[1], lo[2], lo[3]);
}

__global__ void reset_flags_kernel() { g_flags[threadIdx.x] = 0; }

// ---------------- mma.sync recurrence: 128 CTAs, M=32 (8j x 4 gates) x N=64, K split over 8 warps ----------------
__global__ void __launch_bounds__(256, 1)
recur_mma_kernel(const float* __restrict__ gx, float* __restrict__ hseq, int layer)
{
    extern __shared__ float Rbuf[];   // [8 warps][32 rows][RSTR] f32

    const int tid  = threadIdx.x;
    const int w    = tid >> 5;
    const int lane = tid & 31;
    const int cta  = blockIdx.x;

    // register-resident A fragments (fp16 hi/lo)
    unsigned Ah[2][8][4], Al[2][8][4];
    {
        const uint4* wf = (const uint4*)g_WF +
            ((((size_t)(layer * 128 + cta) * 8 + w) * 16) * 32 + lane) * 2;
#pragma unroll
        for (int mt = 0; mt < 2; ++mt)
#pragma unroll
            for (int kt = 0; kt < 8; ++kt) {
                const uint4* p = wf + (size_t)(mt * 8 + kt) * 64;
                uint4 h = p[0], lv = p[1];
                Ah[mt][kt][0] = h.x;  Ah[mt][kt][1] = h.y;  Ah[mt][kt][2] = h.z;  Ah[mt][kt][3] = h.w;
                Al[mt][kt][0] = lv.x; Al[mt][kt][1] = lv.y; Al[mt][kt][2] = lv.z; Al[mt][kt][3] = lv.w;
            }
    }

    const int n   = tid & 63;
    const int jl0 = tid >> 6;          // 0..3
    float cs0 = 0.f, cs1 = 0.f;

    volatile int* vf = (volatile int*)g_flags;

    for (int t = 0; t < S_; ++t) {
        if (t > 0) {
            // parallel per-CTA flag poll (no atomic serialization)
            if (tid < NCTA) { while (vf[tid] < t) {} }
            __syncthreads();
            __threadfence();

            float acc[2][8][4];
#pragma unroll
            for (int mt = 0; mt < 2; ++mt)
#pragma unroll
                for (int nt = 0; nt < 8; ++nt)
#pragma unroll
                    for (int q = 0; q < 4; ++q) acc[mt][nt][q] = 0.f;

            const uint2* hb = (const uint2*)g_hfrag + (size_t)((t - 1) & 1) * 16384;
#pragma unroll
            for (int kt = 0; kt < 8; ++kt) {
                const uint2* kb = hb + ((size_t)(w * 8 + kt) * 8) * 32 + lane;
#pragma unroll
                for (int nt = 0; nt < 8; ++nt) {
                    uint2 Bv = kb[nt * 32];
                    mma16816(acc[0][nt], Ah[0][kt], Bv.x, Bv.y);
                    mma16816(acc[1][nt], Ah[1][kt], Bv.x, Bv.y);
                    mma16816(acc[0][nt], Al[0][kt], Bv.x, Bv.y);
                    mma16816(acc[1][nt], Al[1][kt], Bv.x, Bv.y);
                }
            }

            // store k-partials to smem
            {
                const int r0 = lane >> 2;
                const int c0 = (lane & 3) * 2;
#pragma unroll
                for (int mt = 0; mt < 2; ++mt)
#pragma unroll
                    for (int nt = 0; nt < 8; ++nt) {
                        float* dst = Rbuf + ((size_t)w * 32 + mt * 16 + r0) * RSTR + nt * 8 + c0;
                        *(float2*)dst = make_float2(acc[mt][nt][0], acc[mt][nt][1]);
                        *(float2*)(dst + 8 * RSTR) = make_float2(acc[mt][nt][2], acc[mt][nt][3]);
                    }
            }
        }
        __syncthreads();

        // ---------------- reduction + epilogue (2 cells per thread) ----------------
        unsigned char* hfd = g_hfrag + (size_t)(t & 1) * 131072;
#pragma unroll
        for (int ci = 0; ci < 2; ++ci) {
            int jloc = jl0 + ci * 4;
            int j = cta * 8 + jloc;
            const float* gp = gx + ((size_t)t * G4_ + j) * B_ + n;
            float pi = gp[0];
            float pf = gp[(size_t)1 * H_ * B_];
            float pg = gp[(size_t)2 * H_ * B_];
            float po = gp[(size_t)3 * H_ * B_];
            if (t > 0) {
#pragma unroll
                for (int w8 = 0; w8 < 8; ++w8) {
                    const float* rp = Rbuf + ((size_t)w8 * 32 + jloc * 4) * RSTR + n;
                    pi += rp[0];
                    pf += rp[RSTR];
                    pg += rp[2 * RSTR];
                    po += rp[3 * RSTR];
                }
            }
            float iv = sigf(pi), fv = sigf(pf), gv = tanhf_(pg), ov = sigf(po);
            float& cs = ci ? cs1 : cs0;
            cs = fv * cs + iv * gv;
            float h = ov * tanhf_(cs);
            hseq[((size_t)t * H_ + j) * B_ + n] = h;

            // h fragment (fp16, single product term on B side)
            unsigned short hh = f16of(h);
            int ktile = j >> 4, kk = j & 15;
            int ntile = n >> 3, nn = n & 7;
            int flane = nn * 4 + ((kk & 7) >> 1);
            size_t byte = (((size_t)ktile * 8 + ntile) * 32 + flane) * 8 + (kk >> 3) * 4 + (kk & 1) * 2;
            *(unsigned short*)(hfd + byte) = hh;
        }

        __threadfence();
        __syncthreads();
        if (tid == 0) *((volatile int*)g_flags + cta) = t + 1;
    }
}

// ---------------- fused transpose + sigmoid(relu) ----------------
__global__ void __launch_bounds__(256)
act_out_kernel(const float* __restrict__ h2, float* __restrict__ out)
{
    __shared__ float T[64][68];
    const int s = blockIdx.y, jt = blockIdx.x, t = threadIdx.x;
    {
        int jj0 = (t >> 4) * 4, bq = (t & 15) * 4;
#pragma unroll
        for (int r = 0; r < 4; ++r)
            *(float4*)&T[jj0 + r][bq] =
                *(const float4*)(h2 + ((size_t)s * H_ + jt * 64 + jj0 + r) * B_ + bq);
    }
    __syncthreads();
    {
        int b0 = (t >> 4) * 4, jq = (t & 15) * 4;
#pragma unroll
        for (int i = 0; i < 4; ++i) {
            int b = b0 + i;
            float4 w;
            w.x = actf(T[jq + 0][b]); w.y = actf(T[jq + 1][b]);
            w.z = actf(T[jq + 2][b]); w.w = actf(T[jq + 3][b]);
            *(float4*)(out + (size_t)b * (S_ * H_) + (size_t)s * H_ + jt * 64 + jq) = w;
        }
    }
}

// ---------------- launcher ----------------
extern "C" void kernel_launch(void* const* d_in, const int* in_sizes, int n_in,
                              void* d_out, int out_size)
{
    const float* x    = (const float*)d_in[0];
    const float* Wih0 = (const float*)d_in[1];
    const float* Whh0 = (const float*)d_in[2];
    const float* bih0 = (const float*)d_in[3];
    const float* bhh0 = (const float*)d_in[4];
    const float* Wih1 = (const float*)d_in[5];
    const float* Whh1 = (const float*)d_in[6];
    const float* bih1 = (const float*)d_in[7];
    const float* bhh1 = (const float*)d_in[8];
    float* out = (float*)d_out;

    float *gx, *h1, *h2;
    cudaGetSymbolAddress((void**)&gx, g_gx);
    cudaGetSymbolAddress((void**)&h1, g_h1);
    cudaGetSymbolAddress((void**)&h2, g_h2);

    const int smem_rec = 8 * 32 * RSTR * (int)sizeof(float);   // 67584
    cudaFuncSetAttribute(recur_mma_kernel, cudaFuncAttributeMaxDynamicSharedMemorySize, smem_rec);

    dim3 ggrid(G4_ / 128, S_);

    prep_w_kernel<<<4096, 256>>>(Whh0, Whh1);

    gemm_gx_kernel<D_, 0><<<ggrid, 256>>>(Wih0, x, bih0, bhh0, gx);
    reset_flags_kernel<<<1, 256>>>();
    recur_mma_kernel<<<NCTA, 256, smem_rec>>>(gx, h1, 0);

    gemm_gx_kernel<H_, 1><<<ggrid, 256>>>(Wih1, h1, bih1, bhh1, gx);
    reset_flags_kernel<<<1, 256>>>();
    recur_mma_kernel<<<NCTA, 256, smem_rec>>>(gx, h2, 1);

    dim3 agrid(H_ / 64, S_);
    act_out_kernel<<<agrid, 256>>>(h2, out);
}

// round 8
// speedup vs baseline: 1.3257x; 1.3257x over previous
#include <cuda_runtime.h>
#include <cuda_bf16.h>
#include <cuda_fp16.h>
#include <cstdint>
#include <cstddef>

#define B_   64
#define S_   256
#define D_   512
#define H_   1024
#define G4_  4096
#define NCTA 128
#define RSTR 66   // Rbuf row stride in floats (264B, multiple of 8B)
#define EPOCH 255 // g_flags slot used as broadcast epoch

// ---------------- scratch (device globals) ----------------
__device__ __align__(128) float g_gx[67108864];            // [S][4H][B]
__device__ __align__(128) float g_h1[16777216];            // [S][H][B]
__device__ __align__(128) float g_h2[16777216];            // [S][H][B]
__device__ __align__(128) unsigned char g_WF[33554432];    // A fragments (fp16 hi/lo)
__device__ __align__(128) unsigned char g_hfrag[262144];   // [buf][ktile 64][ntp 4][lane 32][uint4 {ntEven uint2, ntOdd uint2}]
__device__ int g_flags[256];

// ---------------- helpers ----------------
__device__ __forceinline__ unsigned long long pk2(float x, float y) {
    unsigned long long r; asm("mov.b64 %0, {%1, %2};" : "=l"(r) : "f"(x), "f"(y)); return r;
}
__device__ __forceinline__ float2 upk2(unsigned long long v) {
    float2 r; asm("mov.b64 {%0, %1}, %2;" : "=f"(r.x), "=f"(r.y) : "l"(v)); return r;
}
__device__ __forceinline__ void fma2(unsigned long long& d, unsigned long long a, unsigned long long b) {
    asm("fma.rn.f32x2 %0, %1, %2, %0;" : "+l"(d) : "l"(a), "l"(b));
}
__device__ __forceinline__ float sigf(float x)   { return 1.f / (1.f + __expf(-x)); }
__device__ __forceinline__ float tanhf_(float x) { return 2.f / (1.f + __expf(-2.f * x)) - 1.f; }
__device__ __forceinline__ float actf(float x)   { return x > 0.f ? 1.f / (1.f + __expf(-x)) : 0.5f; }

__device__ __forceinline__ unsigned short f16of(float v) {
    __half h = __float2half(v);
    return *(unsigned short*)&h;
}
__device__ __forceinline__ float f16val(unsigned short u) {
    __half h = *(__half*)&u;
    return __half2float(h);
}

__device__ __forceinline__ void mma16816(float* d, const unsigned* a, unsigned b0, unsigned b1) {
    asm volatile("mma.sync.aligned.m16n8k16.row.col.f32.f16.f16.f32 "
                 "{%0,%1,%2,%3}, {%4,%5,%6,%7}, {%8,%9}, {%0,%1,%2,%3};"
                 : "+f"(d[0]), "+f"(d[1]), "+f"(d[2]), "+f"(d[3])
                 : "r"(a[0]), "r"(a[1]), "r"(a[2]), "r"(a[3]), "r"(b0), "r"(b1));
}

// ---------------- input GEMM (FFMA2) ----------------
template<int KDIM, int MODEB>
__global__ void __launch_bounds__(256)
gemm_gx_kernel(const float* __restrict__ W, const float* __restrict__ X,
               const float* __restrict__ bA, const float* __restrict__ bB,
               float* __restrict__ gx)
{
    __shared__ float As[16][132];
    __shared__ float Bs[16][68];
    const int s  = blockIdx.y, gt = blockIdx.x, t = threadIdx.x;
    const int tx = t & 15, ty = t >> 4;
    const int b0 = tx * 4, g0 = ty * 8;
    unsigned long long acc[8][2];
#pragma unroll
    for (int i = 0; i < 8; ++i) { acc[i][0] = 0ull; acc[i][1] = 0ull; }
    const int rA = t >> 1, cA = (t & 1) * 8;

    for (int kt = 0; kt < KDIM / 16; ++kt) {
        {
            const float* src = W + (size_t)(gt * 128 + rA) * KDIM + kt * 16 + cA;
            float4 a0 = *(const float4*)src;
            float4 a1 = *(const float4*)(src + 4);
            As[cA + 0][rA] = a0.x; As[cA + 1][rA] = a0.y; As[cA + 2][rA] = a0.z; As[cA + 3][rA] = a0.w;
            As[cA + 4][rA] = a1.x; As[cA + 5][rA] = a1.y; As[cA + 6][rA] = a1.z; As[cA + 7][rA] = a1.w;
        }
        if (MODEB == 0) {
            int bb = t >> 2, q = (t & 3) * 4;
            float4 v = *(const float4*)(X + ((size_t)bb * S_ + s) * KDIM + kt * 16 + q);
            Bs[q + 0][bb] = v.x; Bs[q + 1][bb] = v.y; Bs[q + 2][bb] = v.z; Bs[q + 3][bb] = v.w;
        } else {
            int dk = t >> 4, bb = (t & 15) * 4;
            float4 v = *(const float4*)(X + ((size_t)s * KDIM + kt * 16 + dk) * B_ + bb);
            *(float4*)&Bs[dk][bb] = v;
        }
        __syncthreads();
#pragma unroll
        for (int k = 0; k < 16; ++k) {
            float4 a0 = *(const float4*)&As[k][g0];
            float4 a1 = *(const float4*)&As[k][g0 + 4];
            float4 bv = *(const float4*)&Bs[k][b0];
            unsigned long long bp0 = pk2(bv.x, bv.y), bp1 = pk2(bv.z, bv.w), av;
            av = pk2(a0.x, a0.x); fma2(acc[0][0], av, bp0); fma2(acc[0][1], av, bp1);
            av = pk2(a0.y, a0.y); fma2(acc[1][0], av, bp0); fma2(acc[1][1], av, bp1);
            av = pk2(a0.z, a0.z); fma2(acc[2][0], av, bp0); fma2(acc[2][1], av, bp1);
            av = pk2(a0.w, a0.w); fma2(acc[3][0], av, bp0); fma2(acc[3][1], av, bp1);
            av = pk2(a1.x, a1.x); fma2(acc[4][0], av, bp0); fma2(acc[4][1], av, bp1);
            av = pk2(a1.y, a1.y); fma2(acc[5][0], av, bp0); fma2(acc[5][1], av, bp1);
            av = pk2(a1.z, a1.z); fma2(acc[6][0], av, bp0); fma2(acc[6][1], av, bp1);
            av = pk2(a1.w, a1.w); fma2(acc[7][0], av, bp0); fma2(acc[7][1], av, bp1);
        }
        __syncthreads();
    }
#pragma unroll
    for (int gi = 0; gi < 8; ++gi) {
        int g = gt * 128 + g0 + gi;
        float bias = bA[g] + bB[g];
        float2 p0 = upk2(acc[gi][0]), p1 = upk2(acc[gi][1]);
        *(float4*)(gx + ((size_t)s * G4_ + g) * B_ + b0) =
            make_float4(p0.x + bias, p0.y + bias, p1.x + bias, p1.y + bias);
    }
}

// ---------------- weight prep: Whh -> per-thread mma A fragments (fp16 hi/lo split) ----------------
__global__ void __launch_bounds__(256)
prep_w_kernel(const float* __restrict__ Whh0, const float* __restrict__ Whh1)
{
    unsigned idx  = blockIdx.x * 256 + threadIdx.x;   // 2^20
    unsigned lane = idx & 31;
    unsigned kt   = (idx >> 5) & 7;
    unsigned mt   = (idx >> 8) & 1;
    unsigned w    = (idx >> 9) & 7;
    unsigned cta  = (idx >> 12) & 127;
    unsigned l    = idx >> 19;
    const float* W = l ? Whh1 : Whh0;

    unsigned hi[4], lo[4];
#pragma unroll
    for (int p = 0; p < 4; ++p) {
        unsigned r = (lane >> 2) + (p & 1) * 8;
        unsigned c = (lane & 3) * 2 + (p >> 1) * 8;
        unsigned rloc = mt * 16 + r;
        unsigned gr = cta * 32 + rloc;
        unsigned j = gr >> 2, gate = gr & 3;
        unsigned k = w * 128 + kt * 16 + c;
        float2 v = *(const float2*)(W + ((size_t)(gate * H_ + j)) * H_ + k);
        unsigned short h0 = f16of(v.x);
        unsigned short l0 = f16of(v.x - f16val(h0));
        unsigned short h1 = f16of(v.y);
        unsigned short l1 = f16of(v.y - f16val(h1));
        hi[p] = (unsigned)h0 | ((unsigned)h1 << 16);
        lo[p] = (unsigned)l0 | ((unsigned)l1 << 16);
    }
    size_t fr = ((((size_t)(l * 128 + cta) * 8 + w) * 2 + mt) * 8 + kt) * 32 + lane;
    uint4* dst = (uint4*)g_WF + fr * 2;
    dst[0] = make_uint4(hi[0], hi[1], hi[2], hi[3]);
    dst[1] = make_uint4(lo[0], lo[1], lo[2], lo[3]);
}

__global__ void reset_flags_kernel() { g_flags[threadIdx.x] = 0; }

// ---------------- mma.sync recurrence: 128 CTAs, M=32 x N=64, K split over 8 warps ----------------
// Sync: producers store flags[cta]=t+1; CTA0 aggregates (128 lanes poll 128 flags) and
// publishes flags[EPOCH]=t; all other CTAs poll the single epoch word (read-only broadcast).
__global__ void __launch_bounds__(256, 1)
recur_mma_kernel(const float* __restrict__ gx, float* __restrict__ hseq, int layer)
{
    extern __shared__ float Rbuf[];   // [8 warps][32 rows][RSTR] f32

    const int tid  = threadIdx.x;
    const int w    = tid >> 5;
    const int lane = tid & 31;
    const int cta  = blockIdx.x;

    // register-resident A fragments (fp16 hi/lo)
    unsigned Ah[2][8][4], Al[2][8][4];
    {
        const uint4* wf = (const uint4*)g_WF +
            ((((size_t)(layer * 128 + cta) * 8 + w) * 16) * 32 + lane) * 2;
#pragma unroll
        for (int mt = 0; mt < 2; ++mt)
#pragma unroll
            for (int kt = 0; kt < 8; ++kt) {
                const uint4* p = wf + (size_t)(mt * 8 + kt) * 64;
                uint4 h = p[0], lv = p[1];
                Ah[mt][kt][0] = h.x;  Ah[mt][kt][1] = h.y;  Ah[mt][kt][2] = h.z;  Ah[mt][kt][3] = h.w;
                Al[mt][kt][0] = lv.x; Al[mt][kt][1] = lv.y; Al[mt][kt][2] = lv.z; Al[mt][kt][3] = lv.w;
            }
    }

    const int n   = tid & 63;
    const int jl0 = tid >> 6;          // 0..3
    float cs0 = 0.f, cs1 = 0.f;

    volatile int* vf = (volatile int*)g_flags;

    for (int t = 0; t < S_; ++t) {
        // prefetch gx for this step's epilogue (independent of the flags)
        float pre[2][4];
#pragma unroll
        for (int ci = 0; ci < 2; ++ci) {
            int j = cta * 8 + jl0 + ci * 4;
            const float* gp = gx + ((size_t)t * G4_ + j) * B_ + n;
            pre[ci][0] = gp[0];
            pre[ci][1] = gp[(size_t)1 * H_ * B_];
            pre[ci][2] = gp[(size_t)2 * H_ * B_];
            pre[ci][3] = gp[(size_t)3 * H_ * B_];
        }

        if (t > 0) {
            if (cta == 0) {
                if (tid < NCTA) { while (vf[tid] < t) {} }
                __syncthreads();
                if (tid == 0) vf[EPOCH] = t;
            } else {
                if (tid == 0) { while (vf[EPOCH] < t) {} }
                __syncthreads();
            }
            __threadfence();

            float acc[2][8][4];
#pragma unroll
            for (int mt = 0; mt < 2; ++mt)
#pragma unroll
                for (int nt = 0; nt < 8; ++nt)
#pragma unroll
                    for (int q = 0; q < 4; ++q) acc[mt][nt][q] = 0.f;

            const uint4* hb = (const uint4*)g_hfrag + (size_t)((t - 1) & 1) * 8192;
#pragma unroll
            for (int kt = 0; kt < 8; ++kt) {
                const uint4* kb = hb + ((size_t)(w * 8 + kt) * 4) * 32 + lane;
#pragma unroll
                for (int ntp = 0; ntp < 4; ++ntp) {
                    uint4 Bv = kb[ntp * 32];
                    int nt0 = ntp * 2, nt1 = ntp * 2 + 1;
                    mma16816(acc[0][nt0], Ah[0][kt], Bv.x, Bv.y);
                    mma16816(acc[1][nt0], Ah[1][kt], Bv.x, Bv.y);
                    mma16816(acc[0][nt0], Al[0][kt], Bv.x, Bv.y);
                    mma16816(acc[1][nt0], Al[1][kt], Bv.x, Bv.y);
                    mma16816(acc[0][nt1], Ah[0][kt], Bv.z, Bv.w);
                    mma16816(acc[1][nt1], Ah[1][kt], Bv.z, Bv.w);
                    mma16816(acc[0][nt1], Al[0][kt], Bv.z, Bv.w);
                    mma16816(acc[1][nt1], Al[1][kt], Bv.z, Bv.w);
                }
            }

            // store k-partials to smem
            {
                const int r0 = lane >> 2;
                const int c0 = (lane & 3) * 2;
#pragma unroll
                for (int mt = 0; mt < 2; ++mt)
#pragma unroll
                    for (int nt = 0; nt < 8; ++nt) {
                        float* dst = Rbuf + ((size_t)w * 32 + mt * 16 + r0) * RSTR + nt * 8 + c0;
                        *(float2*)dst = make_float2(acc[mt][nt][0], acc[mt][nt][1]);
                        *(float2*)(dst + 8 * RSTR) = make_float2(acc[mt][nt][2], acc[mt][nt][3]);
                    }
            }
        }
        __syncthreads();

        // ---------------- reduction + epilogue (2 cells per thread) ----------------
        unsigned char* hfd = g_hfrag + (size_t)(t & 1) * 131072;
        float hval[2];
#pragma unroll
        for (int ci = 0; ci < 2; ++ci) {
            int jloc = jl0 + ci * 4;
            int j = cta * 8 + jloc;
            float pi = pre[ci][0], pf = pre[ci][1], pg = pre[ci][2], po = pre[ci][3];
            if (t > 0) {
#pragma unroll
                for (int w8 = 0; w8 < 8; ++w8) {
                    const float* rp = Rbuf + ((size_t)w8 * 32 + jloc * 4) * RSTR + n;
                    pi += rp[0];
                    pf += rp[RSTR];
                    pg += rp[2 * RSTR];
                    po += rp[3 * RSTR];
                }
            }
            float iv = sigf(pi), fv = sigf(pf), gv = tanhf_(pg), ov = sigf(po);
            float& cs = ci ? cs1 : cs0;
            cs = fv * cs + iv * gv;
            float h = ov * tanhf_(cs);
            hval[ci] = h;

            // h fragment (fp16), ntile-pair uint4 layout
            unsigned short hh = f16of(h);
            int ktile = j >> 4, kk = j & 15;
            int nt = n >> 3;
            int flane = (n & 7) * 4 + ((kk & 7) >> 1);
            size_t byte = (((size_t)(ktile * 4 + (nt >> 1)) * 32 + flane) * 16)
                          + (size_t)(nt & 1) * 8 + (kk >> 3) * 4 + (kk & 1) * 2;
            *(unsigned short*)(hfd + byte) = hh;
        }

        __threadfence();
        __syncthreads();
        if (tid == 0) *((volatile int*)g_flags + cta) = t + 1;

        // fp32 h stores: off the inter-CTA critical path (consumed post-kernel)
#pragma unroll
        for (int ci = 0; ci < 2; ++ci) {
            int j = cta * 8 + jl0 + ci * 4;
            hseq[((size_t)t * H_ + j) * B_ + n] = hval[ci];
        }
    }
}

// ---------------- fused transpose + sigmoid(relu) ----------------
__global__ void __launch_bounds__(256)
act_out_kernel(const float* __restrict__ h2, float* __restrict__ out)
{
    __shared__ float T[64][68];
    const int s = blockIdx.y, jt = blockIdx.x, t = threadIdx.x;
    {
        int jj0 = (t >> 4) * 4, bq = (t & 15) * 4;
#pragma unroll
        for (int r = 0; r < 4; ++r)
            *(float4*)&T[jj0 + r][bq] =
                *(const float4*)(h2 + ((size_t)s * H_ + jt * 64 + jj0 + r) * B_ + bq);
    }
    __syncthreads();
    {
        int b0 = (t >> 4) * 4, jq = (t & 15) * 4;
#pragma unroll
        for (int i = 0; i < 4; ++i) {
            int b = b0 + i;
            float4 w;
            w.x = actf(T[jq + 0][b]); w.y = actf(T[jq + 1][b]);
            w.z = actf(T[jq + 2][b]); w.w = actf(T[jq + 3][b]);
            *(float4*)(out + (size_t)b * (S_ * H_) + (size_t)s * H_ + jt * 64 + jq) = w;
        }
    }
}

// ---------------- launcher ----------------
extern "C" void kernel_launch(void* const* d_in, const int* in_sizes, int n_in,
                              void* d_out, int out_size)
{
    const float* x    = (const float*)d_in[0];
    const float* Wih0 = (const float*)d_in[1];
    const float* Whh0 = (const float*)d_in[2];
    const float* bih0 = (const float*)d_in[3];
    const float* bhh0 = (const float*)d_in[4];
    const float* Wih1 = (const float*)d_in[5];
    const float* Whh1 = (const float*)d_in[6];
    const float* bih1 = (const float*)d_in[7];
    const float* bhh1 = (const float*)d_in[8];
    float* out = (float*)d_out;

    float *gx, *h1, *h2;
    cudaGetSymbolAddress((void**)&gx, g_gx);
    cudaGetSymbolAddress((void**)&h1, g_h1);
    cudaGetSymbolAddress((void**)&h2, g_h2);

    const int smem_rec = 8 * 32 * RSTR * (int)sizeof(float);   // 67584
    cudaFuncSetAttribute(recur_mma_kernel, cudaFuncAttributeMaxDynamicSharedMemorySize, smem_rec);

    dim3 ggrid(G4_ / 128, S_);

    prep_w_kernel<<<4096, 256>>>(Whh0, Whh1);

    gemm_gx_kernel<D_, 0><<<ggrid, 256>>>(Wih0, x, bih0, bhh0, gx);
    reset_flags_kernel<<<1, 256>>>();
    recur_mma_kernel<<<NCTA, 256, smem_rec>>>(gx, h1, 0);

    gemm_gx_kernel<H_, 1><<<ggrid, 256>>>(Wih1, h1, bih1, bhh1, gx);
    reset_flags_kernel<<<1, 256>>>();
    recur_mma_kernel<<<NCTA, 256, smem_rec>>>(gx, h2, 1);

    dim3 agrid(H_ / 64, S_);
    act_out_kernel<<<agrid, 256>>>(h2, out);
}

// round 9
// speedup vs baseline: 2.0097x; 1.5159x over previous
#include <cuda_runtime.h>
#include <cuda_bf16.h>
#include <cuda_fp16.h>
#include <cstdint>
#include <cstddef>

#define B_   64
#define S_   256
#define D_   512
#define H_   1024
#define G4_  4096
#define NCTA 128
#define RSTR 66
#define EPOCH 255

// ---------------- scratch (device globals) ----------------
__device__ __align__(128) float g_gx[67108864];            // [S][4H][B]
__device__ __align__(128) float g_h1[16777216];            // [S][H][B]
__device__ __align__(128) float g_h2[16777216];            // [S][H][B]
__device__ __align__(128) unsigned char g_WF[33554432];    // recurrence A fragments (fp16 hi/lo)
__device__ __align__(128) unsigned char g_WI[25165824];    // input-GEMM A fragments (fp16 hi/lo)
__device__ __align__(128) unsigned char g_xf[33554432];    // input-GEMM B fragments (fp16)
__device__ __align__(128) unsigned char g_hfrag[262144];   // recurrence h fragments
__device__ int g_flags[256];

// ---------------- helpers ----------------
__device__ __forceinline__ float sigf(float x)   { return 1.f / (1.f + __expf(-x)); }
__device__ __forceinline__ float tanhf_(float x) { return 2.f / (1.f + __expf(-2.f * x)) - 1.f; }
__device__ __forceinline__ float actf(float x)   { return x > 0.f ? 1.f / (1.f + __expf(-x)) : 0.5f; }

__device__ __forceinline__ unsigned short f16of(float v) {
    __half h = __float2half(v);
    return *(unsigned short*)&h;
}
__device__ __forceinline__ float f16val(unsigned short u) {
    __half h = *(__half*)&u;
    return __half2float(h);
}

__device__ __forceinline__ void mma16816(float* d, const unsigned* a, unsigned b0, unsigned b1) {
    asm volatile("mma.sync.aligned.m16n8k16.row.col.f32.f16.f16.f32 "
                 "{%0,%1,%2,%3}, {%4,%5,%6,%7}, {%8,%9}, {%0,%1,%2,%3};"
                 : "+f"(d[0]), "+f"(d[1]), "+f"(d[2]), "+f"(d[3])
                 : "r"(a[0]), "r"(a[1]), "r"(a[2]), "r"(a[3]), "r"(b0), "r"(b1));
}

// B-fragment byte offset within one s (validated by the recurrence path)
__device__ __forceinline__ size_t xf_byte(int k, int n) {
    int ktile = k >> 4, kk = k & 15;
    int nt = n >> 3;
    int flane = (n & 7) * 4 + ((kk & 7) >> 1);
    return (((size_t)(ktile * 4 + (nt >> 1)) * 32 + flane) * 16)
           + (size_t)(nt & 1) * 8 + (kk >> 3) * 4 + (kk & 1) * 2;
}

// ---------------- prep: W_ih -> A fragments (fp16 hi/lo) ----------------
template<int KT, int KDIM>
__global__ void __launch_bounds__(256)
prep_wi_kernel(const float* __restrict__ W, size_t base_u4)
{
    unsigned idx  = blockIdx.x * 256 + threadIdx.x;   // 32*8*KT*32 threads
    unsigned lane = idx & 31;
    unsigned kt   = (idx >> 5) & (KT - 1);
    unsigned w    = (idx >> 5) / KT & 7;
    unsigned gt   = (idx >> 5) / KT >> 3;

    unsigned hi[4], lo[4];
#pragma unroll
    for (int p = 0; p < 4; ++p) {
        unsigned r = (lane >> 2) + (p & 1) * 8;
        unsigned c = (lane & 3) * 2 + (p >> 1) * 8;
        unsigned row = gt * 128 + w * 16 + r;
        unsigned k = kt * 16 + c;
        float2 v = *(const float2*)(W + (size_t)row * KDIM + k);
        unsigned short h0 = f16of(v.x);
        unsigned short l0 = f16of(v.x - f16val(h0));
        unsigned short h1 = f16of(v.y);
        unsigned short l1 = f16of(v.y - f16val(h1));
        hi[p] = (unsigned)h0 | ((unsigned)h1 << 16);
        lo[p] = (unsigned)l0 | ((unsigned)l1 << 16);
    }
    size_t fu = ((size_t)(gt * 8 + w) * KT + kt) * 32 + lane;
    uint4* dst = (uint4*)g_WI + base_u4 + fu * 2;
    dst[0] = make_uint4(hi[0], hi[1], hi[2], hi[3]);
    dst[1] = make_uint4(lo[0], lo[1], lo[2], lo[3]);
}

// ---------------- conv: x [B][S][D] -> B fragments (K=512) ----------------
__global__ void __launch_bounds__(256)
conv_x0_kernel(const float* __restrict__ x)
{
    unsigned idx = blockIdx.x * 256 + threadIdx.x;    // 256*64*128
    unsigned k4  = idx & 127;
    unsigned n   = (idx >> 7) & 63;
    unsigned s   = idx >> 13;
    float4 v = *(const float4*)(x + ((size_t)n * S_ + s) * D_ + k4 * 4);
    unsigned char* bs = g_xf + (size_t)s * 65536;     // KT=32: 32*4*32*16 bytes per s
    int k = k4 * 4;
    unsigned u0 = (unsigned)f16of(v.x) | ((unsigned)f16of(v.y) << 16);
    unsigned u1 = (unsigned)f16of(v.z) | ((unsigned)f16of(v.w) << 16);
    *(unsigned*)(bs + xf_byte(k, n))     = u0;
    *(unsigned*)(bs + xf_byte(k + 2, n)) = u1;
}

// ---------------- conv: h1 [S][H][B] -> B fragments (K=1024) ----------------
__global__ void __launch_bounds__(256)
conv_h1_kernel(const float* __restrict__ h1)
{
    unsigned idx = blockIdx.x * 256 + threadIdx.x;    // 256*1024*16
    unsigned n4  = idx & 15;
    unsigned k   = (idx >> 4) & 1023;
    unsigned s   = idx >> 14;
    float4 v = *(const float4*)(h1 + ((size_t)s * H_ + k) * B_ + n4 * 4);
    unsigned char* bs = g_xf + (size_t)s * 131072;    // KT=64
    int n = n4 * 4;
    *(unsigned short*)(bs + xf_byte(k, n))     = f16of(v.x);
    *(unsigned short*)(bs + xf_byte(k, n + 1)) = f16of(v.y);
    *(unsigned short*)(bs + xf_byte(k, n + 2)) = f16of(v.z);
    *(unsigned short*)(bs + xf_byte(k, n + 3)) = f16of(v.w);
}

// ---------------- tensor-core input GEMM: gx[s][g][b] (2 s per CTA) ----------------
template<int KT>
__global__ void __launch_bounds__(256)
gemm_mma_kernel(const uint4* __restrict__ WI, const uint4* __restrict__ XF,
                const float* __restrict__ bA, const float* __restrict__ bB,
                float* __restrict__ gx)
{
    const int tid = threadIdx.x, w = tid >> 5, lane = tid & 31;
    const int gt = blockIdx.x;
    const int s0 = blockIdx.y * 2;

    float acc[2][8][4];
#pragma unroll
    for (int si = 0; si < 2; ++si)
#pragma unroll
        for (int nt = 0; nt < 8; ++nt)
#pragma unroll
            for (int q = 0; q < 4; ++q) acc[si][nt][q] = 0.f;

    const uint4* ap  = WI + (((size_t)(gt * 8 + w) * KT) * 32 + lane) * 2;
    const uint4* bp0 = XF + (size_t)s0 * (KT * 128) + lane;
    const uint4* bp1 = bp0 + KT * 128;

    for (int kt = 0; kt < KT; ++kt) {
        uint4 AhV = ap[0], AlV = ap[1]; ap += 64;
        unsigned Ah[4] = {AhV.x, AhV.y, AhV.z, AhV.w};
        unsigned Al[4] = {AlV.x, AlV.y, AlV.z, AlV.w};
        const uint4* q0 = bp0 + kt * 128;
        const uint4* q1 = bp1 + kt * 128;
#pragma unroll
        for (int ntp = 0; ntp < 4; ++ntp) {
            uint4 B0 = q0[ntp * 32];
            mma16816(acc[0][ntp * 2],     Ah, B0.x, B0.y);
            mma16816(acc[0][ntp * 2],     Al, B0.x, B0.y);
            mma16816(acc[0][ntp * 2 + 1], Ah, B0.z, B0.w);
            mma16816(acc[0][ntp * 2 + 1], Al, B0.z, B0.w);
            uint4 B1 = q1[ntp * 32];
            mma16816(acc[1][ntp * 2],     Ah, B1.x, B1.y);
            mma16816(acc[1][ntp * 2],     Al, B1.x, B1.y);
            mma16816(acc[1][ntp * 2 + 1], Ah, B1.z, B1.w);
            mma16816(acc[1][ntp * 2 + 1], Al, B1.z, B1.w);
        }
    }

    const int r0 = lane >> 2, c0 = (lane & 3) * 2;
    const int gl = gt * 128 + w * 16 + r0;
    const float biasL = bA[gl] + bB[gl];
    const float biasH = bA[gl + 8] + bB[gl + 8];
#pragma unroll
    for (int si = 0; si < 2; ++si) {
        float* gxs = gx + (size_t)(s0 + si) * G4_ * B_;
#pragma unroll
        for (int nt = 0; nt < 8; ++nt) {
            int c = nt * 8 + c0;
            *(float2*)(gxs + (size_t)gl * B_ + c) =
                make_float2(acc[si][nt][0] + biasL, acc[si][nt][1] + biasL);
            *(float2*)(gxs + (size_t)(gl + 8) * B_ + c) =
                make_float2(acc[si][nt][2] + biasH, acc[si][nt][3] + biasH);
        }
    }
}

// ---------------- weight prep: Whh -> recurrence A fragments (fp16 hi/lo) ----------------
__global__ void __launch_bounds__(256)
prep_w_kernel(const float* __restrict__ Whh0, const float* __restrict__ Whh1)
{
    unsigned idx  = blockIdx.x * 256 + threadIdx.x;
    unsigned lane = idx & 31;
    unsigned kt   = (idx >> 5) & 7;
    unsigned mt   = (idx >> 8) & 1;
    unsigned w    = (idx >> 9) & 7;
    unsigned cta  = (idx >> 12) & 127;
    unsigned l    = idx >> 19;
    const float* W = l ? Whh1 : Whh0;

    unsigned hi[4], lo[4];
#pragma unroll
    for (int p = 0; p < 4; ++p) {
        unsigned r = (lane >> 2) + (p & 1) * 8;
        unsigned c = (lane & 3) * 2 + (p >> 1) * 8;
        unsigned rloc = mt * 16 + r;
        unsigned gr = cta * 32 + rloc;
        unsigned j = gr >> 2, gate = gr & 3;
        unsigned k = w * 128 + kt * 16 + c;
        float2 v = *(const float2*)(W + ((size_t)(gate * H_ + j)) * H_ + k);
        unsigned short h0 = f16of(v.x);
        unsigned short l0 = f16of(v.x - f16val(h0));
        unsigned short h1 = f16of(v.y);
        unsigned short l1 = f16of(v.y - f16val(h1));
        hi[p] = (unsigned)h0 | ((unsigned)h1 << 16);
        lo[p] = (unsigned)l0 | ((unsigned)l1 << 16);
    }
    size_t fr = ((((size_t)(l * 128 + cta) * 8 + w) * 2 + mt) * 8 + kt) * 32 + lane;
    uint4* dst = (uint4*)g_WF + fr * 2;
    dst[0] = make_uint4(hi[0], hi[1], hi[2], hi[3]);
    dst[1] = make_uint4(lo[0], lo[1], lo[2], lo[3]);
}

__global__ void reset_flags_kernel() { g_flags[threadIdx.x] = 0; }

// ---------------- mma.sync recurrence (unchanged from R8) ----------------
__global__ void __launch_bounds__(256, 1)
recur_mma_kernel(const float* __restrict__ gx, float* __restrict__ hseq, int layer)
{
    extern __shared__ float Rbuf[];

    const int tid  = threadIdx.x;
    const int w    = tid >> 5;
    const int lane = tid & 31;
    const int cta  = blockIdx.x;

    unsigned Ah[2][8][4], Al[2][8][4];
    {
        const uint4* wf = (const uint4*)g_WF +
            ((((size_t)(layer * 128 + cta) * 8 + w) * 16) * 32 + lane) * 2;
#pragma unroll
        for (int mt = 0; mt < 2; ++mt)
#pragma unroll
            for (int kt = 0; kt < 8; ++kt) {
                const uint4* p = wf + (size_t)(mt * 8 + kt) * 64;
                uint4 h = p[0], lv = p[1];
                Ah[mt][kt][0] = h.x;  Ah[mt][kt][1] = h.y;  Ah[mt][kt][2] = h.z;  Ah[mt][kt][3] = h.w;
                Al[mt][kt][0] = lv.x; Al[mt][kt][1] = lv.y; Al[mt][kt][2] = lv.z; Al[mt][kt][3] = lv.w;
            }
    }

    const int n   = tid & 63;
    const int jl0 = tid >> 6;
    float cs0 = 0.f, cs1 = 0.f;

    volatile int* vf = (volatile int*)g_flags;

    for (int t = 0; t < S_; ++t) {
        float pre[2][4];
#pragma unroll
        for (int ci = 0; ci < 2; ++ci) {
            int j = cta * 8 + jl0 + ci * 4;
            const float* gp = gx + ((size_t)t * G4_ + j) * B_ + n;
            pre[ci][0] = gp[0];
            pre[ci][1] = gp[(size_t)1 * H_ * B_];
            pre[ci][2] = gp[(size_t)2 * H_ * B_];
            pre[ci][3] = gp[(size_t)3 * H_ * B_];
        }

        if (t > 0) {
            if (cta == 0) {
                if (tid < NCTA) { while (vf[tid] < t) {} }
                __syncthreads();
                if (tid == 0) vf[EPOCH] = t;
            } else {
                if (tid == 0) { while (vf[EPOCH] < t) {} }
                __syncthreads();
            }
            __threadfence();

            float acc[2][8][4];
#pragma unroll
            for (int mt = 0; mt < 2; ++mt)
#pragma unroll
                for (int nt = 0; nt < 8; ++nt)
#pragma unroll
                    for (int q = 0; q < 4; ++q) acc[mt][nt][q] = 0.f;

            const uint4* hb = (const uint4*)g_hfrag + (size_t)((t - 1) & 1) * 8192;
#pragma unroll
            for (int kt = 0; kt < 8; ++kt) {
                const uint4* kb = hb + ((size_t)(w * 8 + kt) * 4) * 32 + lane;
#pragma unroll
                for (int ntp = 0; ntp < 4; ++ntp) {
                    uint4 Bv = kb[ntp * 32];
                    int nt0 = ntp * 2, nt1 = ntp * 2 + 1;
                    mma16816(acc[0][nt0], Ah[0][kt], Bv.x, Bv.y);
                    mma16816(acc[1][nt0], Ah[1][kt], Bv.x, Bv.y);
                    mma16816(acc[0][nt0], Al[0][kt], Bv.x, Bv.y);
                    mma16816(acc[1][nt0], Al[1][kt], Bv.x, Bv.y);
                    mma16816(acc[0][nt1], Ah[0][kt], Bv.z, Bv.w);
                    mma16816(acc[1][nt1], Ah[1][kt], Bv.z, Bv.w);
                    mma16816(acc[0][nt1], Al[0][kt], Bv.z, Bv.w);
                    mma16816(acc[1][nt1], Al[1][kt], Bv.z, Bv.w);
                }
            }

            {
                const int r0 = lane >> 2;
                const int c0 = (lane & 3) * 2;
#pragma unroll
                for (int mt = 0; mt < 2; ++mt)
#pragma unroll
                    for (int nt = 0; nt < 8; ++nt) {
                        float* dst = Rbuf + ((size_t)w * 32 + mt * 16 + r0) * RSTR + nt * 8 + c0;
                        *(float2*)dst = make_float2(acc[mt][nt][0], acc[mt][nt][1]);
                        *(float2*)(dst + 8 * RSTR) = make_float2(acc[mt][nt][2], acc[mt][nt][3]);
                    }
            }
        }
        __syncthreads();

        unsigned char* hfd = g_hfrag + (size_t)(t & 1) * 131072;
        float hval[2];
#pragma unroll
        for (int ci = 0; ci < 2; ++ci) {
            int jloc = jl0 + ci * 4;
            int j = cta * 8 + jloc;
            float pi = pre[ci][0], pf = pre[ci][1], pg = pre[ci][2], po = pre[ci][3];
            if (t > 0) {
#pragma unroll
                for (int w8 = 0; w8 < 8; ++w8) {
                    const float* rp = Rbuf + ((size_t)w8 * 32 + jloc * 4) * RSTR + n;
                    pi += rp[0];
                    pf += rp[RSTR];
                    pg += rp[2 * RSTR];
                    po += rp[3 * RSTR];
                }
            }
            float iv = sigf(pi), fv = sigf(pf), gv = tanhf_(pg), ov = sigf(po);
            float& cs = ci ? cs1 : cs0;
            cs = fv * cs + iv * gv;
            float h = ov * tanhf_(cs);
            hval[ci] = h;

            unsigned short hh = f16of(h);
            int ktile = j >> 4, kk = j & 15;
            int nt = n >> 3;
            int flane = (n & 7) * 4 + ((kk & 7) >> 1);
            size_t byte = (((size_t)(ktile * 4 + (nt >> 1)) * 32 + flane) * 16)
                          + (size_t)(nt & 1) * 8 + (kk >> 3) * 4 + (kk & 1) * 2;
            *(unsigned short*)(hfd + byte) = hh;
        }

        __threadfence();
        __syncthreads();
        if (tid == 0) *((volatile int*)g_flags + cta) = t + 1;

#pragma unroll
        for (int ci = 0; ci < 2; ++ci) {
            int j = cta * 8 + jl0 + ci * 4;
            hseq[((size_t)t * H_ + j) * B_ + n] = hval[ci];
        }
    }
}

// ---------------- fused transpose + sigmoid(relu) ----------------
__global__ void __launch_bounds__(256)
act_out_kernel(const float* __restrict__ h2, float* __restrict__ out)
{
    __shared__ float T[64][68];
    const int s = blockIdx.y, jt = blockIdx.x, t = threadIdx.x;
    {
        int jj0 = (t >> 4) * 4, bq = (t & 15) * 4;
#pragma unroll
        for (int r = 0; r < 4; ++r)
            *(float4*)&T[jj0 + r][bq] =
                *(const float4*)(h2 + ((size_t)s * H_ + jt * 64 + jj0 + r) * B_ + bq);
    }
    __syncthreads();
    {
        int b0 = (t >> 4) * 4, jq = (t & 15) * 4;
#pragma unroll
        for (int i = 0; i < 4; ++i) {
            int b = b0 + i;
            float4 w;
            w.x = actf(T[jq + 0][b]); w.y = actf(T[jq + 1][b]);
            w.z = actf(T[jq + 2][b]); w.w = actf(T[jq + 3][b]);
            *(float4*)(out + (size_t)b * (S_ * H_) + (size_t)s * H_ + jt * 64 + jq) = w;
        }
    }
}

// ---------------- launcher ----------------
extern "C" void kernel_launch(void* const* d_in, const int* in_sizes, int n_in,
                              void* d_out, int out_size)
{
    const float* x    = (const float*)d_in[0];
    const float* Wih0 = (const float*)d_in[1];
    const float* Whh0 = (const float*)d_in[2];
    const float* bih0 = (const float*)d_in[3];
    const float* bhh0 = (const float*)d_in[4];
    const float* Wih1 = (const float*)d_in[5];
    const float* Whh1 = (const float*)d_in[6];
    const float* bih1 = (const float*)d_in[7];
    const float* bhh1 = (const float*)d_in[8];
    float* out = (float*)d_out;

    float *gx, *h1, *h2;
    unsigned char* wi;
    unsigned char* xf;
    cudaGetSymbolAddress((void**)&gx, g_gx);
    cudaGetSymbolAddress((void**)&h1, g_h1);
    cudaGetSymbolAddress((void**)&h2, g_h2);
    cudaGetSymbolAddress((void**)&wi, g_WI);
    cudaGetSymbolAddress((void**)&xf, g_xf);

    const int smem_rec = 8 * 32 * RSTR * (int)sizeof(float);   // 67584
    cudaFuncSetAttribute(recur_mma_kernel, cudaFuncAttributeMaxDynamicSharedMemorySize, smem_rec);

    // one-shot preps (independent)
    prep_w_kernel<<<4096, 256>>>(Whh0, Whh1);
    prep_wi_kernel<32, D_><<<1024, 256>>>(Wih0, 0);
    prep_wi_kernel<64, H_><<<2048, 256>>>(Wih1, 524288);
    conv_x0_kernel<<<8192, 256>>>(x);

    dim3 ggrid(32, 128);

    // Layer 0
    gemm_mma_kernel<32><<<ggrid, 256>>>((const uint4*)wi, (const uint4*)xf, bih0, bhh0, gx);
    reset_flags_kernel<<<1, 256>>>();
    recur_mma_kernel<<<NCTA, 256, smem_rec>>>(gx, h1, 0);

    // Layer 1
    conv_h1_kernel<<<16384, 256>>>(h1);
    gemm_mma_kernel<64><<<ggrid, 256>>>((const uint4*)wi + 524288, (const uint4*)xf, bih1, bhh1, gx);
    reset_flags_kernel<<<1, 256>>>();
    recur_mma_kernel<<<NCTA, 256, smem_rec>>>(gx, h2, 1);

    // Epilogue
    dim3 agrid(H_ / 64, S_);
    act_out_kernel<<<agrid, 256>>>(h2, out);
}

// round 10
// speedup vs baseline: 2.4923x; 1.2401x over previous
#include <cuda_runtime.h>
#include <cuda_bf16.h>
#include <cuda_fp16.h>
#include <cstdint>
#include <cstddef>

#define B_   64
#define S_   256
#define D_   512
#define H_   1024
#define G4_  4096
#define NCTA 128
#define RSTR 66
#define EPOCH 255

// ---------------- scratch (device globals) ----------------
__device__ __align__(128) float g_gx[67108864];            // [S][4H][B]
__device__ __align__(128) float g_h1[16777216];            // [S][H][B]
__device__ __align__(128) float g_h2[16777216];            // [S][H][B]
__device__ __align__(128) unsigned char g_WF[33554432];    // recurrence A fragments (fp16, hi used)
__device__ __align__(128) unsigned char g_WI[25165824];    // input-GEMM A fragments (fp16, hi used)
__device__ __align__(128) unsigned char g_xf[33554432];    // input-GEMM B fragments (fp16)
__device__ __align__(128) unsigned char g_hfrag[262144];   // recurrence h fragments
__device__ int g_flags[256];

// ---------------- helpers ----------------
__device__ __forceinline__ float sigf(float x)   { return 1.f / (1.f + __expf(-x)); }
__device__ __forceinline__ float tanhf_(float x) { return 2.f / (1.f + __expf(-2.f * x)) - 1.f; }
__device__ __forceinline__ float actf(float x)   { return x > 0.f ? 1.f / (1.f + __expf(-x)) : 0.5f; }

__device__ __forceinline__ unsigned short f16of(float v) {
    __half h = __float2half(v);
    return *(unsigned short*)&h;
}
__device__ __forceinline__ float f16val(unsigned short u) {
    __half h = *(__half*)&u;
    return __half2float(h);
}

__device__ __forceinline__ void mma16816(float* d, const unsigned* a, unsigned b0, unsigned b1) {
    asm volatile("mma.sync.aligned.m16n8k16.row.col.f32.f16.f16.f32 "
                 "{%0,%1,%2,%3}, {%4,%5,%6,%7}, {%8,%9}, {%0,%1,%2,%3};"
                 : "+f"(d[0]), "+f"(d[1]), "+f"(d[2]), "+f"(d[3])
                 : "r"(a[0]), "r"(a[1]), "r"(a[2]), "r"(a[3]), "r"(b0), "r"(b1));
}

// B-fragment byte offset within one s (validated layout)
__device__ __forceinline__ size_t xf_byte(int k, int n) {
    int ktile = k >> 4, kk = k & 15;
    int nt = n >> 3;
    int flane = (n & 7) * 4 + ((kk & 7) >> 1);
    return (((size_t)(ktile * 4 + (nt >> 1)) * 32 + flane) * 16)
           + (size_t)(nt & 1) * 8 + (kk >> 3) * 4 + (kk & 1) * 2;
}

// ---------------- prep: W_ih -> A fragments (fp16) ----------------
template<int KT, int KDIM>
__global__ void __launch_bounds__(256)
prep_wi_kernel(const float* __restrict__ W, size_t base_u4)
{
    unsigned idx  = blockIdx.x * 256 + threadIdx.x;
    unsigned lane = idx & 31;
    unsigned kt   = (idx >> 5) & (KT - 1);
    unsigned w    = (idx >> 5) / KT & 7;
    unsigned gt   = (idx >> 5) / KT >> 3;

    unsigned hi[4];
#pragma unroll
    for (int p = 0; p < 4; ++p) {
        unsigned r = (lane >> 2) + (p & 1) * 8;
        unsigned c = (lane & 3) * 2 + (p >> 1) * 8;
        unsigned row = gt * 128 + w * 16 + r;
        unsigned k = kt * 16 + c;
        float2 v = *(const float2*)(W + (size_t)row * KDIM + k);
        hi[p] = (unsigned)f16of(v.x) | ((unsigned)f16of(v.y) << 16);
    }
    size_t fu = ((size_t)(gt * 8 + w) * KT + kt) * 32 + lane;
    uint4* dst = (uint4*)g_WI + base_u4 + fu;
    dst[0] = make_uint4(hi[0], hi[1], hi[2], hi[3]);
}

// ---------------- conv: x [B][S][D] -> B fragments (K=512) ----------------
__global__ void __launch_bounds__(256)
conv_x0_kernel(const float* __restrict__ x)
{
    unsigned idx = blockIdx.x * 256 + threadIdx.x;
    unsigned k4  = idx & 127;
    unsigned n   = (idx >> 7) & 63;
    unsigned s   = idx >> 13;
    float4 v = *(const float4*)(x + ((size_t)n * S_ + s) * D_ + k4 * 4);
    unsigned char* bs = g_xf + (size_t)s * 65536;
    int k = k4 * 4;
    unsigned u0 = (unsigned)f16of(v.x) | ((unsigned)f16of(v.y) << 16);
    unsigned u1 = (unsigned)f16of(v.z) | ((unsigned)f16of(v.w) << 16);
    *(unsigned*)(bs + xf_byte(k, n))     = u0;
    *(unsigned*)(bs + xf_byte(k + 2, n)) = u1;
}

// ---------------- conv: h1 [S][H][B] -> B fragments (K=1024) ----------------
__global__ void __launch_bounds__(256)
conv_h1_kernel(const float* __restrict__ h1)
{
    unsigned idx = blockIdx.x * 256 + threadIdx.x;
    unsigned n4  = idx & 15;
    unsigned k   = (idx >> 4) & 1023;
    unsigned s   = idx >> 14;
    float4 v = *(const float4*)(h1 + ((size_t)s * H_ + k) * B_ + n4 * 4);
    unsigned char* bs = g_xf + (size_t)s * 131072;
    int n = n4 * 4;
    *(unsigned short*)(bs + xf_byte(k, n))     = f16of(v.x);
    *(unsigned short*)(bs + xf_byte(k, n + 1)) = f16of(v.y);
    *(unsigned short*)(bs + xf_byte(k, n + 2)) = f16of(v.z);
    *(unsigned short*)(bs + xf_byte(k, n + 3)) = f16of(v.w);
}

// ---------------- tensor-core input GEMM: gx[s][g][b] (2 s per CTA, single product) ----------------
template<int KT>
__global__ void __launch_bounds__(256)
gemm_mma_kernel(const uint4* __restrict__ WI, const uint4* __restrict__ XF,
                const float* __restrict__ bA, const float* __restrict__ bB,
                float* __restrict__ gx)
{
    const int tid = threadIdx.x, w = tid >> 5, lane = tid & 31;
    const int gt = blockIdx.x;
    const int s0 = blockIdx.y * 2;

    float acc[2][8][4];
#pragma unroll
    for (int si = 0; si < 2; ++si)
#pragma unroll
        for (int nt = 0; nt < 8; ++nt)
#pragma unroll
            for (int q = 0; q < 4; ++q) acc[si][nt][q] = 0.f;

    const uint4* ap  = WI + ((size_t)(gt * 8 + w) * KT) * 32 + lane;
    const uint4* bp0 = XF + (size_t)s0 * (KT * 128) + lane;
    const uint4* bp1 = bp0 + KT * 128;

    for (int kt = 0; kt < KT; ++kt) {
        uint4 AhV = ap[0]; ap += 32;
        unsigned Ah[4] = {AhV.x, AhV.y, AhV.z, AhV.w};
        const uint4* q0 = bp0 + kt * 128;
        const uint4* q1 = bp1 + kt * 128;
#pragma unroll
        for (int ntp = 0; ntp < 4; ++ntp) {
            uint4 B0 = q0[ntp * 32];
            mma16816(acc[0][ntp * 2],     Ah, B0.x, B0.y);
            mma16816(acc[0][ntp * 2 + 1], Ah, B0.z, B0.w);
            uint4 B1 = q1[ntp * 32];
            mma16816(acc[1][ntp * 2],     Ah, B1.x, B1.y);
            mma16816(acc[1][ntp * 2 + 1], Ah, B1.z, B1.w);
        }
    }

    const int r0 = lane >> 2, c0 = (lane & 3) * 2;
    const int gl = gt * 128 + w * 16 + r0;
    const float biasL = bA[gl] + bB[gl];
    const float biasH = bA[gl + 8] + bB[gl + 8];
#pragma unroll
    for (int si = 0; si < 2; ++si) {
        float* gxs = gx + (size_t)(s0 + si) * G4_ * B_;
#pragma unroll
        for (int nt = 0; nt < 8; ++nt) {
            int c = nt * 8 + c0;
            *(float2*)(gxs + (size_t)gl * B_ + c) =
                make_float2(acc[si][nt][0] + biasL, acc[si][nt][1] + biasL);
            *(float2*)(gxs + (size_t)(gl + 8) * B_ + c) =
                make_float2(acc[si][nt][2] + biasH, acc[si][nt][3] + biasH);
        }
    }
}

// ---------------- weight prep: Whh -> recurrence A fragments (fp16) ----------------
__global__ void __launch_bounds__(256)
prep_w_kernel(const float* __restrict__ Whh0, const float* __restrict__ Whh1)
{
    unsigned idx  = blockIdx.x * 256 + threadIdx.x;
    unsigned lane = idx & 31;
    unsigned kt   = (idx >> 5) & 7;
    unsigned mt   = (idx >> 8) & 1;
    unsigned w    = (idx >> 9) & 7;
    unsigned cta  = (idx >> 12) & 127;
    unsigned l    = idx >> 19;
    const float* W = l ? Whh1 : Whh0;

    unsigned hi[4];
#pragma unroll
    for (int p = 0; p < 4; ++p) {
        unsigned r = (lane >> 2) + (p & 1) * 8;
        unsigned c = (lane & 3) * 2 + (p >> 1) * 8;
        unsigned rloc = mt * 16 + r;
        unsigned gr = cta * 32 + rloc;
        unsigned j = gr >> 2, gate = gr & 3;
        unsigned k = w * 128 + kt * 16 + c;
        float2 v = *(const float2*)(W + ((size_t)(gate * H_ + j)) * H_ + k);
        hi[p] = (unsigned)f16of(v.x) | ((unsigned)f16of(v.y) << 16);
    }
    size_t fr = ((((size_t)(l * 128 + cta) * 8 + w) * 2 + mt) * 8 + kt) * 32 + lane;
    uint4* dst = (uint4*)g_WF + fr;
    dst[0] = make_uint4(hi[0], hi[1], hi[2], hi[3]);
}

__global__ void reset_flags_kernel() { g_flags[threadIdx.x] = 0; }

// ---------------- mma.sync recurrence: single fp16 product ----------------
__global__ void __launch_bounds__(256, 1)
recur_mma_kernel(const float* __restrict__ gx, float* __restrict__ hseq, int layer)
{
    extern __shared__ float Rbuf[];

    const int tid  = threadIdx.x;
    const int w    = tid >> 5;
    const int lane = tid & 31;
    const int cta  = blockIdx.x;

    unsigned Ah[2][8][4];
    {
        const uint4* wf = (const uint4*)g_WF +
            (((size_t)(layer * 128 + cta) * 8 + w) * 16) * 32 + lane;
#pragma unroll
        for (int mt = 0; mt < 2; ++mt)
#pragma unroll
            for (int kt = 0; kt < 8; ++kt) {
                uint4 h = wf[(size_t)(mt * 8 + kt) * 32];
                Ah[mt][kt][0] = h.x; Ah[mt][kt][1] = h.y; Ah[mt][kt][2] = h.z; Ah[mt][kt][3] = h.w;
            }
    }

    const int n   = tid & 63;
    const int jl0 = tid >> 6;
    float cs0 = 0.f, cs1 = 0.f;

    volatile int* vf = (volatile int*)g_flags;

    for (int t = 0; t < S_; ++t) {
        float pre[2][4];
#pragma unroll
        for (int ci = 0; ci < 2; ++ci) {
            int j = cta * 8 + jl0 + ci * 4;
            const float* gp = gx + ((size_t)t * G4_ + j) * B_ + n;
            pre[ci][0] = gp[0];
            pre[ci][1] = gp[(size_t)1 * H_ * B_];
            pre[ci][2] = gp[(size_t)2 * H_ * B_];
            pre[ci][3] = gp[(size_t)3 * H_ * B_];
        }

        if (t > 0) {
            if (cta == 0) {
                if (tid < NCTA) { while (vf[tid] < t) {} }
                __syncthreads();
                if (tid == 0) vf[EPOCH] = t;
            } else {
                if (tid == 0) { while (vf[EPOCH] < t) {} }
                __syncthreads();
            }
            __threadfence();

            float acc[2][8][4];
#pragma unroll
            for (int mt = 0; mt < 2; ++mt)
#pragma unroll
                for (int nt = 0; nt < 8; ++nt)
#pragma unroll
                    for (int q = 0; q < 4; ++q) acc[mt][nt][q] = 0.f;

            const uint4* hb = (const uint4*)g_hfrag + (size_t)((t - 1) & 1) * 8192;
#pragma unroll
            for (int kt = 0; kt < 8; ++kt) {
                const uint4* kb = hb + ((size_t)(w * 8 + kt) * 4) * 32 + lane;
#pragma unroll
                for (int ntp = 0; ntp < 4; ++ntp) {
                    uint4 Bv = kb[ntp * 32];
                    int nt0 = ntp * 2, nt1 = ntp * 2 + 1;
                    mma16816(acc[0][nt0], Ah[0][kt], Bv.x, Bv.y);
                    mma16816(acc[1][nt0], Ah[1][kt], Bv.x, Bv.y);
                    mma16816(acc[0][nt1], Ah[0][kt], Bv.z, Bv.w);
                    mma16816(acc[1][nt1], Ah[1][kt], Bv.z, Bv.w);
                }
            }

            {
                const int r0 = lane >> 2;
                const int c0 = (lane & 3) * 2;
#pragma unroll
                for (int mt = 0; mt < 2; ++mt)
#pragma unroll
                    for (int nt = 0; nt < 8; ++nt) {
                        float* dst = Rbuf + ((size_t)w * 32 + mt * 16 + r0) * RSTR + nt * 8 + c0;
                        *(float2*)dst = make_float2(acc[mt][nt][0], acc[mt][nt][1]);
                        *(float2*)(dst + 8 * RSTR) = make_float2(acc[mt][nt][2], acc[mt][nt][3]);
                    }
            }
        }
        __syncthreads();

        unsigned char* hfd = g_hfrag + (size_t)(t & 1) * 131072;
        float hval[2];
#pragma unroll
        for (int ci = 0; ci < 2; ++ci) {
            int jloc = jl0 + ci * 4;
            int j = cta * 8 + jloc;
            float pi = pre[ci][0], pf = pre[ci][1], pg = pre[ci][2], po = pre[ci][3];
            if (t > 0) {
#pragma unroll
                for (int w8 = 0; w8 < 8; ++w8) {
                    const float* rp = Rbuf + ((size_t)w8 * 32 + jloc * 4) * RSTR + n;
                    pi += rp[0];
                    pf += rp[RSTR];
                    pg += rp[2 * RSTR];
                    po += rp[3 * RSTR];
                }
            }
            float iv = sigf(pi), fv = sigf(pf), gv = tanhf_(pg), ov = sigf(po);
            float& cs = ci ? cs1 : cs0;
            cs = fv * cs + iv * gv;
            float h = ov * tanhf_(cs);
            hval[ci] = h;

            unsigned short hh = f16of(h);
            int ktile = j >> 4, kk = j & 15;
            int nt = n >> 3;
            int flane = (n & 7) * 4 + ((kk & 7) >> 1);
            size_t byte = (((size_t)(ktile * 4 + (nt >> 1)) * 32 + flane) * 16)
                          + (size_t)(nt & 1) * 8 + (kk >> 3) * 4 + (kk & 1) * 2;
            *(unsigned short*)(hfd + byte) = hh;
        }

        __threadfence();
        __syncthreads();
        if (tid == 0) *((volatile int*)g_flags + cta) = t + 1;

#pragma unroll
        for (int ci = 0; ci < 2; ++ci) {
            int j = cta * 8 + jl0 + ci * 4;
            hseq[((size_t)t * H_ + j) * B_ + n] = hval[ci];
        }
    }
}

// ---------------- fused transpose + sigmoid(relu) ----------------
__global__ void __launch_bounds__(256)
act_out_kernel(const float* __restrict__ h2, float* __restrict__ out)
{
    __shared__ float T[64][68];
    const int s = blockIdx.y, jt = blockIdx.x, t = threadIdx.x;
    {
        int jj0 = (t >> 4) * 4, bq = (t & 15) * 4;
#pragma unroll
        for (int r = 0; r < 4; ++r)
            *(float4*)&T[jj0 + r][bq] =
                *(const float4*)(h2 + ((size_t)s * H_ + jt * 64 + jj0 + r) * B_ + bq);
    }
    __syncthreads();
    {
        int b0 = (t >> 4) * 4, jq = (t & 15) * 4;
#pragma unroll
        for (int i = 0; i < 4; ++i) {
            int b = b0 + i;
            float4 w;
            w.x = actf(T[jq + 0][b]); w.y = actf(T[jq + 1][b]);
            w.z = actf(T[jq + 2][b]); w.w = actf(T[jq + 3][b]);
            *(float4*)(out + (size_t)b * (S_ * H_) + (size_t)s * H_ + jt * 64 + jq) = w;
        }
    }
}

// ---------------- launcher ----------------
extern "C" void kernel_launch(void* const* d_in, const int* in_sizes, int n_in,
                              void* d_out, int out_size)
{
    const float* x    = (const float*)d_in[0];
    const float* Wih0 = (const float*)d_in[1];
    const float* Whh0 = (const float*)d_in[2];
    const float* bih0 = (const float*)d_in[3];
    const float* bhh0 = (const float*)d_in[4];
    const float* Wih1 = (const float*)d_in[5];
    const float* Whh1 = (const float*)d_in[6];
    const float* bih1 = (const float*)d_in[7];
    const float* bhh1 = (const float*)d_in[8];
    float* out = (float*)d_out;

    float *gx, *h1, *h2;
    unsigned char* wi;
    unsigned char* xf;
    cudaGetSymbolAddress((void**)&gx, g_gx);
    cudaGetSymbolAddress((void**)&h1, g_h1);
    cudaGetSymbolAddress((void**)&h2, g_h2);
    cudaGetSymbolAddress((void**)&wi, g_WI);
    cudaGetSymbolAddress((void**)&xf, g_xf);

    const int smem_rec = 8 * 32 * RSTR * (int)sizeof(float);   // 67584
    cudaFuncSetAttribute(recur_mma_kernel, cudaFuncAttributeMaxDynamicSharedMemorySize, smem_rec);

    // one-shot preps
    prep_w_kernel<<<4096, 256>>>(Whh0, Whh1);
    prep_wi_kernel<32, D_><<<1024, 256>>>(Wih0, 0);
    prep_wi_kernel<64, H_><<<2048, 256>>>(Wih1, 262144);
    conv_x0_kernel<<<8192, 256>>>(x);

    dim3 ggrid(32, 128);

    // Layer 0
    gemm_mma_kernel<32><<<ggrid, 256>>>((const uint4*)wi, (const uint4*)xf, bih0, bhh0, gx);
    reset_flags_kernel<<<1, 256>>>();
    recur_mma_kernel<<<NCTA, 256, smem_rec>>>(gx, h1, 0);

    // Layer 1
    conv_h1_kernel<<<16384, 256>>>(h1);
    gemm_mma_kernel<64><<<ggrid, 256>>>((const uint4*)wi + 262144, (const uint4*)xf, bih1, bhh1, gx);
    reset_flags_kernel<<<1, 256>>>();
    recur_mma_kernel<<<NCTA, 256, smem_rec>>>(gx, h2, 1);

    // Epilogue
    dim3 agrid(H_ / 64, S_);
    act_out_kernel<<<agrid, 256>>>(h2, out);
}

// round 11
// speedup vs baseline: 3.3741x; 1.3538x over previous
#include <cuda_runtime.h>
#include <cuda_bf16.h>
#include <cuda_fp16.h>
#include <cstdint>
#include <cstddef>

#define B_   64
#define S_   256
#define D_   512
#define H_   1024
#define G4_  4096
#define NCTA 128
#define RSTR 66
#define EPOCH 255

// ---------------- scratch (device globals) ----------------
__device__ __align__(128) float g_gx[67108864];            // [S][4H][B] (layer0 only)
__device__ __align__(128) float g_h2[16777216];            // [S][H][B]
__device__ __align__(128) unsigned char g_WF[33554432];    // A fragments: slot0=Whh0, slot1=Whh1, slot2=Wih1
__device__ __align__(128) unsigned char g_WI[8388608];     // layer0 input-GEMM A fragments
__device__ __align__(128) unsigned char g_xf[16777216];    // layer0 input-GEMM B fragments
__device__ __align__(128) unsigned char g_h1frag[262144];  // [buf][...] h1 fragments (fp16)
__device__ __align__(128) unsigned char g_h2frag[262144];  // [buf][...] h2 fragments (fp16)
__device__ int g_flags[256];

// ---------------- helpers ----------------
__device__ __forceinline__ float sigf(float x)   { return 1.f / (1.f + __expf(-x)); }
__device__ __forceinline__ float tanhf_(float x) { return 2.f / (1.f + __expf(-2.f * x)) - 1.f; }
__device__ __forceinline__ float actf(float x)   { return x > 0.f ? 1.f / (1.f + __expf(-x)) : 0.5f; }

__device__ __forceinline__ unsigned short f16of(float v) {
    __half h = __float2half(v);
    return *(unsigned short*)&h;
}

__device__ __forceinline__ void mma16816(float* d, const unsigned* a, unsigned b0, unsigned b1) {
    asm volatile("mma.sync.aligned.m16n8k16.row.col.f32.f16.f16.f32 "
                 "{%0,%1,%2,%3}, {%4,%5,%6,%7}, {%8,%9}, {%0,%1,%2,%3};"
                 : "+f"(d[0]), "+f"(d[1]), "+f"(d[2]), "+f"(d[3])
                 : "r"(a[0]), "r"(a[1]), "r"(a[2]), "r"(a[3]), "r"(b0), "r"(b1));
}

// B-fragment byte offset within one s (validated layout)
__device__ __forceinline__ size_t xf_byte(int k, int n) {
    int ktile = k >> 4, kk = k & 15;
    int nt = n >> 3;
    int flane = (n & 7) * 4 + ((kk & 7) >> 1);
    return (((size_t)(ktile * 4 + (nt >> 1)) * 32 + flane) * 16)
           + (size_t)(nt & 1) * 8 + (kk >> 3) * 4 + (kk & 1) * 2;
}

// ---------------- prep: W_ih0 -> A fragments (fp16) ----------------
template<int KT, int KDIM>
__global__ void __launch_bounds__(256)
prep_wi_kernel(const float* __restrict__ W)
{
    unsigned idx  = blockIdx.x * 256 + threadIdx.x;
    unsigned lane = idx & 31;
    unsigned kt   = (idx >> 5) & (KT - 1);
    unsigned w    = (idx >> 5) / KT & 7;
    unsigned gt   = (idx >> 5) / KT >> 3;

    unsigned hi[4];
#pragma unroll
    for (int p = 0; p < 4; ++p) {
        unsigned r = (lane >> 2) + (p & 1) * 8;
        unsigned c = (lane & 3) * 2 + (p >> 1) * 8;
        unsigned row = gt * 128 + w * 16 + r;
        unsigned k = kt * 16 + c;
        float2 v = *(const float2*)(W + (size_t)row * KDIM + k);
        hi[p] = (unsigned)f16of(v.x) | ((unsigned)f16of(v.y) << 16);
    }
    size_t fu = ((size_t)(gt * 8 + w) * KT + kt) * 32 + lane;
    ((uint4*)g_WI)[fu] = make_uint4(hi[0], hi[1], hi[2], hi[3]);
}

// ---------------- conv: x [B][S][D] -> B fragments (K=512) ----------------
__global__ void __launch_bounds__(256)
conv_x0_kernel(const float* __restrict__ x)
{
    unsigned idx = blockIdx.x * 256 + threadIdx.x;
    unsigned k4  = idx & 127;
    unsigned n   = (idx >> 7) & 63;
    unsigned s   = idx >> 13;
    float4 v = *(const float4*)(x + ((size_t)n * S_ + s) * D_ + k4 * 4);
    unsigned char* bs = g_xf + (size_t)s * 65536;
    int k = k4 * 4;
    unsigned u0 = (unsigned)f16of(v.x) | ((unsigned)f16of(v.y) << 16);
    unsigned u1 = (unsigned)f16of(v.z) | ((unsigned)f16of(v.w) << 16);
    *(unsigned*)(bs + xf_byte(k, n))     = u0;
    *(unsigned*)(bs + xf_byte(k + 2, n)) = u1;
}

// ---------------- tensor-core layer0 input GEMM: gx[s][g][b] ----------------
template<int KT>
__global__ void __launch_bounds__(256)
gemm_mma_kernel(const uint4* __restrict__ WI, const uint4* __restrict__ XF,
                const float* __restrict__ bA, const float* __restrict__ bB,
                float* __restrict__ gx)
{
    const int tid = threadIdx.x, w = tid >> 5, lane = tid & 31;
    const int gt = blockIdx.x;
    const int s0 = blockIdx.y * 2;

    float acc[2][8][4];
#pragma unroll
    for (int si = 0; si < 2; ++si)
#pragma unroll
        for (int nt = 0; nt < 8; ++nt)
#pragma unroll
            for (int q = 0; q < 4; ++q) acc[si][nt][q] = 0.f;

    const uint4* ap  = WI + ((size_t)(gt * 8 + w) * KT) * 32 + lane;
    const uint4* bp0 = XF + (size_t)s0 * (KT * 128) + lane;
    const uint4* bp1 = bp0 + KT * 128;

    for (int kt = 0; kt < KT; ++kt) {
        uint4 AhV = ap[0]; ap += 32;
        unsigned Ah[4] = {AhV.x, AhV.y, AhV.z, AhV.w};
        const uint4* q0 = bp0 + kt * 128;
        const uint4* q1 = bp1 + kt * 128;
#pragma unroll
        for (int ntp = 0; ntp < 4; ++ntp) {
            uint4 B0 = q0[ntp * 32];
            mma16816(acc[0][ntp * 2],     Ah, B0.x, B0.y);
            mma16816(acc[0][ntp * 2 + 1], Ah, B0.z, B0.w);
            uint4 B1 = q1[ntp * 32];
            mma16816(acc[1][ntp * 2],     Ah, B1.x, B1.y);
            mma16816(acc[1][ntp * 2 + 1], Ah, B1.z, B1.w);
        }
    }

    const int r0 = lane >> 2, c0 = (lane & 3) * 2;
    const int gl = gt * 128 + w * 16 + r0;
    const float biasL = bA[gl] + bB[gl];
    const float biasH = bA[gl + 8] + bB[gl + 8];
#pragma unroll
    for (int si = 0; si < 2; ++si) {
        float* gxs = gx + (size_t)(s0 + si) * G4_ * B_;
#pragma unroll
        for (int nt = 0; nt < 8; ++nt) {
            int c = nt * 8 + c0;
            *(float2*)(gxs + (size_t)gl * B_ + c) =
                make_float2(acc[si][nt][0] + biasL, acc[si][nt][1] + biasL);
            *(float2*)(gxs + (size_t)(gl + 8) * B_ + c) =
                make_float2(acc[si][nt][2] + biasH, acc[si][nt][3] + biasH);
        }
    }
}

// ---------------- weight prep: {Whh0, Whh1, Wih1} -> gate-interleaved A fragments ----------------
__global__ void __launch_bounds__(256)
prep_w_kernel(const float* __restrict__ Whh0, const float* __restrict__ Whh1,
              const float* __restrict__ Wih1)
{
    unsigned idx  = blockIdx.x * 256 + threadIdx.x;   // 3 * 2^19 threads
    unsigned lane = idx & 31;
    unsigned kt   = (idx >> 5) & 7;
    unsigned mt   = (idx >> 8) & 1;
    unsigned w    = (idx >> 9) & 7;
    unsigned cta  = (idx >> 12) & 127;
    unsigned l    = idx >> 19;                        // 0,1,2
    const float* W = (l == 0) ? Whh0 : (l == 1 ? Whh1 : Wih1);

    unsigned hi[4];
#pragma unroll
    for (int p = 0; p < 4; ++p) {
        unsigned r = (lane >> 2) + (p & 1) * 8;
        unsigned c = (lane & 3) * 2 + (p >> 1) * 8;
        unsigned rloc = mt * 16 + r;
        unsigned gr = cta * 32 + rloc;
        unsigned j = gr >> 2, gate = gr & 3;
        unsigned k = w * 128 + kt * 16 + c;
        float2 v = *(const float2*)(W + ((size_t)(gate * H_ + j)) * H_ + k);
        hi[p] = (unsigned)f16of(v.x) | ((unsigned)f16of(v.y) << 16);
    }
    size_t fr = ((((size_t)(l * 128 + cta) * 8 + w) * 2 + mt) * 8 + kt) * 32 + lane;
    ((uint4*)g_WF)[fr] = make_uint4(hi[0], hi[1], hi[2], hi[3]);
}

__global__ void reset_flags_kernel() { g_flags[threadIdx.x] = 0; }

// ---------------- fused 2-layer wavefront recurrence: 257 supersteps ----------------
// Superstep s: phase A computes h1[s] (s<256); phase B computes h2[s-1] (s>=1).
__global__ void __launch_bounds__(256, 1)
fused_recur_kernel(const float* __restrict__ gx,
                   const float* __restrict__ bih1, const float* __restrict__ bhh1,
                   float* __restrict__ hseq2)
{
    extern __shared__ float Rbuf[];

    const int tid  = threadIdx.x;
    const int w    = tid >> 5;
    const int lane = tid & 31;
    const int cta  = blockIdx.x;

    // resident A: layer0 recurrence (slot 0)
    unsigned A0[2][8][4];
    {
        const uint4* wf = (const uint4*)g_WF + (((size_t)cta * 8 + w) * 16) * 32 + lane;
#pragma unroll
        for (int mt = 0; mt < 2; ++mt)
#pragma unroll
            for (int kt = 0; kt < 8; ++kt) {
                uint4 h = wf[(size_t)(mt * 8 + kt) * 32];
                A0[mt][kt][0] = h.x; A0[mt][kt][1] = h.y; A0[mt][kt][2] = h.z; A0[mt][kt][3] = h.w;
            }
    }
    // streamed A: layer1 recurrence (slot 1) and layer1 input (slot 2)
    const uint4* wfR = (const uint4*)g_WF + (((size_t)(128 + cta) * 8 + w) * 16) * 32 + lane;
    const uint4* wfI = (const uint4*)g_WF + (((size_t)(256 + cta) * 8 + w) * 16) * 32 + lane;

    const int n   = tid & 63;
    const int jl0 = tid >> 6;
    float c0[2] = {0.f, 0.f}, c1[2] = {0.f, 0.f};

    // layer1 biases
    float b1v[2][4];
#pragma unroll
    for (int ci = 0; ci < 2; ++ci) {
        int j = cta * 8 + jl0 + ci * 4;
#pragma unroll
        for (int g = 0; g < 4; ++g) b1v[ci][g] = bih1[g * H_ + j] + bhh1[g * H_ + j];
    }

    volatile int* vf = (volatile int*)g_flags;
    const int r0s = lane >> 2, c0s = (lane & 3) * 2;

    for (int s = 0; s <= S_; ++s) {
        // prefetch gx0[s] (phase A input, flag-independent)
        float pre[2][4];
        if (s < S_) {
#pragma unroll
            for (int ci = 0; ci < 2; ++ci) {
                int j = cta * 8 + jl0 + ci * 4;
                const float* gp = gx + ((size_t)s * G4_ + j) * B_ + n;
                pre[ci][0] = gp[0];
                pre[ci][1] = gp[(size_t)1 * H_ * B_];
                pre[ci][2] = gp[(size_t)2 * H_ * B_];
                pre[ci][3] = gp[(size_t)3 * H_ * B_];
            }
        }

        if (s > 0) {
            if (cta == 0) {
                if (tid < NCTA) { while (vf[tid] < s) {} }
                __syncthreads();
                if (tid == 0) vf[EPOCH] = s;
            } else {
                if (tid == 0) { while (vf[EPOCH] < s) {} }
                __syncthreads();
            }
            __threadfence();
        }

        // ---------------- phase A: layer0, h1[s] ----------------
        if (s < S_) {
            if (s > 0) {
                float acc[2][8][4];
#pragma unroll
                for (int mt = 0; mt < 2; ++mt)
#pragma unroll
                    for (int nt = 0; nt < 8; ++nt)
#pragma unroll
                        for (int q = 0; q < 4; ++q) acc[mt][nt][q] = 0.f;

                const uint4* hb = (const uint4*)g_h1frag + (size_t)((s - 1) & 1) * 8192;
#pragma unroll
                for (int kt = 0; kt < 8; ++kt) {
                    const uint4* kb = hb + ((size_t)(w * 8 + kt) * 4) * 32 + lane;
#pragma unroll
                    for (int ntp = 0; ntp < 4; ++ntp) {
                        uint4 Bv = kb[ntp * 32];
                        mma16816(acc[0][ntp * 2],     A0[0][kt], Bv.x, Bv.y);
                        mma16816(acc[1][ntp * 2],     A0[1][kt], Bv.x, Bv.y);
                        mma16816(acc[0][ntp * 2 + 1], A0[0][kt], Bv.z, Bv.w);
                        mma16816(acc[1][ntp * 2 + 1], A0[1][kt], Bv.z, Bv.w);
                    }
                }
#pragma unroll
                for (int mt = 0; mt < 2; ++mt)
#pragma unroll
                    for (int nt = 0; nt < 8; ++nt) {
                        float* dst = Rbuf + ((size_t)w * 32 + mt * 16 + r0s) * RSTR + nt * 8 + c0s;
                        *(float2*)dst = make_float2(acc[mt][nt][0], acc[mt][nt][1]);
                        *(float2*)(dst + 8 * RSTR) = make_float2(acc[mt][nt][2], acc[mt][nt][3]);
                    }
            }
            __syncthreads();

            unsigned char* hfd = g_h1frag + (size_t)(s & 1) * 131072;
#pragma unroll
            for (int ci = 0; ci < 2; ++ci) {
                int jloc = jl0 + ci * 4;
                int j = cta * 8 + jloc;
                float pi = pre[ci][0], pf = pre[ci][1], pg = pre[ci][2], po = pre[ci][3];
                if (s > 0) {
#pragma unroll
                    for (int w8 = 0; w8 < 8; ++w8) {
                        const float* rp = Rbuf + ((size_t)w8 * 32 + jloc * 4) * RSTR + n;
                        pi += rp[0];
                        pf += rp[RSTR];
                        pg += rp[2 * RSTR];
                        po += rp[3 * RSTR];
                    }
                }
                float iv = sigf(pi), fv = sigf(pf), gv = tanhf_(pg), ov = sigf(po);
                c0[ci] = fv * c0[ci] + iv * gv;
                float h = ov * tanhf_(c0[ci]);

                unsigned short hh = f16of(h);
                int ktile = j >> 4, kk = j & 15;
                int nt = n >> 3;
                int flane = (n & 7) * 4 + ((kk & 7) >> 1);
                size_t byte = (((size_t)(ktile * 4 + (nt >> 1)) * 32 + flane) * 16)
                              + (size_t)(nt & 1) * 8 + (kk >> 3) * 4 + (kk & 1) * 2;
                *(unsigned short*)(hfd + byte) = hh;
            }
        }
        __syncthreads();   // Rbuf reuse + h1frag intra-CTA visibility

        // ---------------- phase B: layer1, h2[s-1] ----------------
        float h2v[2];
        if (s >= 1) {
            float acc[2][8][4];
#pragma unroll
            for (int mt = 0; mt < 2; ++mt)
#pragma unroll
                for (int nt = 0; nt < 8; ++nt)
#pragma unroll
                    for (int q = 0; q < 4; ++q) acc[mt][nt][q] = 0.f;

            // input GEMM: W_ih1 @ h1[s-1]  (A streamed from slot 2)
            {
                const uint4* hb1 = (const uint4*)g_h1frag + (size_t)((s - 1) & 1) * 8192;
#pragma unroll
                for (int kt = 0; kt < 8; ++kt) {
                    uint4 a0v = wfI[(size_t)kt * 32];
                    uint4 a1v = wfI[(size_t)(8 + kt) * 32];
                    unsigned Ai0[4] = {a0v.x, a0v.y, a0v.z, a0v.w};
                    unsigned Ai1[4] = {a1v.x, a1v.y, a1v.z, a1v.w};
                    const uint4* kb = hb1 + ((size_t)(w * 8 + kt) * 4) * 32 + lane;
#pragma unroll
                    for (int ntp = 0; ntp < 4; ++ntp) {
                        uint4 Bv = kb[ntp * 32];
                        mma16816(acc[0][ntp * 2],     Ai0, Bv.x, Bv.y);
                        mma16816(acc[1][ntp * 2],     Ai1, Bv.x, Bv.y);
                        mma16816(acc[0][ntp * 2 + 1], Ai0, Bv.z, Bv.w);
                        mma16816(acc[1][ntp * 2 + 1], Ai1, Bv.z, Bv.w);
                    }
                }
            }
            // recurrence: W_hh1 @ h2[s-2]  (A streamed from slot 1)
            if (s >= 2) {
                const uint4* hb2 = (const uint4*)g_h2frag + (size_t)(s & 1) * 8192;
#pragma unroll
                for (int kt = 0; kt < 8; ++kt) {
                    uint4 a0v = wfR[(size_t)kt * 32];
                    uint4 a1v = wfR[(size_t)(8 + kt) * 32];
                    unsigned Ar0[4] = {a0v.x, a0v.y, a0v.z, a0v.w};
                    unsigned Ar1[4] = {a1v.x, a1v.y, a1v.z, a1v.w};
                    const uint4* kb = hb2 + ((size_t)(w * 8 + kt) * 4) * 32 + lane;
#pragma unroll
                    for (int ntp = 0; ntp < 4; ++ntp) {
                        uint4 Bv = kb[ntp * 32];
                        mma16816(acc[0][ntp * 2],     Ar0, Bv.x, Bv.y);
                        mma16816(acc[1][ntp * 2],     Ar1, Bv.x, Bv.y);
                        mma16816(acc[0][ntp * 2 + 1], Ar0, Bv.z, Bv.w);
                        mma16816(acc[1][ntp * 2 + 1], Ar1, Bv.z, Bv.w);
                    }
                }
            }

#pragma unroll
            for (int mt = 0; mt < 2; ++mt)
#pragma unroll
                for (int nt = 0; nt < 8; ++nt) {
                    float* dst = Rbuf + ((size_t)w * 32 + mt * 16 + r0s) * RSTR + nt * 8 + c0s;
                    *(float2*)dst = make_float2(acc[mt][nt][0], acc[mt][nt][1]);
                    *(float2*)(dst + 8 * RSTR) = make_float2(acc[mt][nt][2], acc[mt][nt][3]);
                }
            __syncthreads();

            unsigned char* hfd2 = g_h2frag + (size_t)((s - 1) & 1) * 131072;
#pragma unroll
            for (int ci = 0; ci < 2; ++ci) {
                int jloc = jl0 + ci * 4;
                int j = cta * 8 + jloc;
                float pi = b1v[ci][0], pf = b1v[ci][1], pg = b1v[ci][2], po = b1v[ci][3];
#pragma unroll
                for (int w8 = 0; w8 < 8; ++w8) {
                    const float* rp = Rbuf + ((size_t)w8 * 32 + jloc * 4) * RSTR + n;
                    pi += rp[0];
                    pf += rp[RSTR];
                    pg += rp[2 * RSTR];
                    po += rp[3 * RSTR];
                }
                float iv = sigf(pi), fv = sigf(pf), gv = tanhf_(pg), ov = sigf(po);
                c1[ci] = fv * c1[ci] + iv * gv;
                float h = ov * tanhf_(c1[ci]);
                h2v[ci] = h;

                unsigned short hh = f16of(h);
                int ktile = j >> 4, kk = j & 15;
                int nt = n >> 3;
                int flane = (n & 7) * 4 + ((kk & 7) >> 1);
                size_t byte = (((size_t)(ktile * 4 + (nt >> 1)) * 32 + flane) * 16)
                              + (size_t)(nt & 1) * 8 + (kk >> 3) * 4 + (kk & 1) * 2;
                *(unsigned short*)(hfd2 + byte) = hh;
            }
        }

        __threadfence();
        __syncthreads();
        if (tid == 0) *((volatile int*)g_flags + cta) = s + 1;

        // fp32 h2 stores: off the inter-CTA critical path
        if (s >= 1) {
#pragma unroll
            for (int ci = 0; ci < 2; ++ci) {
                int j = cta * 8 + jl0 + ci * 4;
                hseq2[((size_t)(s - 1) * H_ + j) * B_ + n] = h2v[ci];
            }
        }
    }
}

// ---------------- fused transpose + sigmoid(relu) ----------------
__global__ void __launch_bounds__(256)
act_out_kernel(const float* __restrict__ h2, float* __restrict__ out)
{
    __shared__ float T[64][68];
    const int s = blockIdx.y, jt = blockIdx.x, t = threadIdx.x;
    {
        int jj0 = (t >> 4) * 4, bq = (t & 15) * 4;
#pragma unroll
        for (int r = 0; r < 4; ++r)
            *(float4*)&T[jj0 + r][bq] =
                *(const float4*)(h2 + ((size_t)s * H_ + jt * 64 + jj0 + r) * B_ + bq);
    }
    __syncthreads();
    {
        int b0 = (t >> 4) * 4, jq = (t & 15) * 4;
#pragma unroll
        for (int i = 0; i < 4; ++i) {
            int b = b0 + i;
            float4 w;
            w.x = actf(T[jq + 0][b]); w.y = actf(T[jq + 1][b]);
            w.z = actf(T[jq + 2][b]); w.w = actf(T[jq + 3][b]);
            *(float4*)(out + (size_t)b * (S_ * H_) + (size_t)s * H_ + jt * 64 + jq) = w;
        }
    }
}

// ---------------- launcher ----------------
extern "C" void kernel_launch(void* const* d_in, const int* in_sizes, int n_in,
                              void* d_out, int out_size)
{
    const float* x    = (const float*)d_in[0];
    const float* Wih0 = (const float*)d_in[1];
    const float* Whh0 = (const float*)d_in[2];
    const float* bih0 = (const float*)d_in[3];
    const float* bhh0 = (const float*)d_in[4];
    const float* Wih1 = (const float*)d_in[5];
    const float* Whh1 = (const float*)d_in[6];
    const float* bih1 = (const float*)d_in[7];
    const float* bhh1 = (const float*)d_in[8];
    float* out = (float*)d_out;

    float *gx, *h2;
    unsigned char* wi;
    unsigned char* xf;
    cudaGetSymbolAddress((void**)&gx, g_gx);
    cudaGetSymbolAddress((void**)&h2, g_h2);
    cudaGetSymbolAddress((void**)&wi, g_WI);
    cudaGetSymbolAddress((void**)&xf, g_xf);

    const int smem_rec = 8 * 32 * RSTR * (int)sizeof(float);   // 67584
    cudaFuncSetAttribute(fused_recur_kernel, cudaFuncAttributeMaxDynamicSharedMemorySize, smem_rec);

    // one-shot preps
    prep_w_kernel<<<6144, 256>>>(Whh0, Whh1, Wih1);
    prep_wi_kernel<32, D_><<<1024, 256>>>(Wih0);
    conv_x0_kernel<<<8192, 256>>>(x);

    // layer0 input GEMM
    dim3 ggrid(32, 128);
    gemm_mma_kernel<32><<<ggrid, 256>>>((const uint4*)wi, (const uint4*)xf, bih0, bhh0, gx);

    // fused two-layer recurrence
    reset_flags_kernel<<<1, 256>>>();
    fused_recur_kernel<<<NCTA, 256, smem_rec>>>(gx, bih1, bhh1, h2);

    // epilogue
    dim3 agrid(H_ / 64, S_);
    act_out_kernel<<<agrid, 256>>>(h2, out);
}

// round 12
// speedup vs baseline: 3.6510x; 1.0821x over previous
#include <cuda_runtime.h>
#include <cuda_bf16.h>
#include <cuda_fp16.h>
#include <cstdint>
#include <cstddef>

#define B_   64
#define S_   256
#define D_   512
#define H_   1024
#define G4_  4096
#define NCTA 128
#define RSTR 66
#define EPOCH 255

// ---------------- scratch (device globals) ----------------
__device__ __align__(128) float g_gx[67108864];            // [S][4H][B] (layer0 only)
__device__ __align__(128) float g_h2[16777216];            // [S][H][B]
__device__ __align__(128) unsigned char g_WF[33554432];    // A fragments: slot0=Whh0, slot1=Whh1, slot2=Wih1
__device__ __align__(128) unsigned char g_WI[8388608];     // layer0 input-GEMM A fragments
__device__ __align__(128) unsigned char g_xf[16777216];    // layer0 input-GEMM B fragments
__device__ __align__(128) unsigned char g_h1frag[262144];  // [buf][...] h1 fragments (fp16)
__device__ __align__(128) unsigned char g_h2frag[262144];  // [buf][...] h2 fragments (fp16)
__device__ int g_flags[256];

// ---------------- helpers ----------------
__device__ __forceinline__ float sigf(float x)   { return 1.f / (1.f + __expf(-x)); }
__device__ __forceinline__ float tanhf_(float x) { return 2.f / (1.f + __expf(-2.f * x)) - 1.f; }
__device__ __forceinline__ float actf(float x)   { return x > 0.f ? 1.f / (1.f + __expf(-x)) : 0.5f; }

__device__ __forceinline__ unsigned short f16of(float v) {
    __half h = __float2half(v);
    return *(unsigned short*)&h;
}

__device__ __forceinline__ void mma16816(float* d, const unsigned* a, unsigned b0, unsigned b1) {
    asm volatile("mma.sync.aligned.m16n8k16.row.col.f32.f16.f16.f32 "
                 "{%0,%1,%2,%3}, {%4,%5,%6,%7}, {%8,%9}, {%0,%1,%2,%3};"
                 : "+f"(d[0]), "+f"(d[1]), "+f"(d[2]), "+f"(d[3])
                 : "r"(a[0]), "r"(a[1]), "r"(a[2]), "r"(a[3]), "r"(b0), "r"(b1));
}

// B-fragment byte offset within one s (validated layout)
__device__ __forceinline__ size_t xf_byte(int k, int n) {
    int ktile = k >> 4, kk = k & 15;
    int nt = n >> 3;
    int flane = (n & 7) * 4 + ((kk & 7) >> 1);
    return (((size_t)(ktile * 4 + (nt >> 1)) * 32 + flane) * 16)
           + (size_t)(nt & 1) * 8 + (kk >> 3) * 4 + (kk & 1) * 2;
}

// ---------------- prep: W_ih0 -> A fragments (fp16) ----------------
template<int KT, int KDIM>
__global__ void __launch_bounds__(256)
prep_wi_kernel(const float* __restrict__ W)
{
    unsigned idx  = blockIdx.x * 256 + threadIdx.x;
    unsigned lane = idx & 31;
    unsigned kt   = (idx >> 5) & (KT - 1);
    unsigned w    = (idx >> 5) / KT & 7;
    unsigned gt   = (idx >> 5) / KT >> 3;

    unsigned hi[4];
#pragma unroll
    for (int p = 0; p < 4; ++p) {
        unsigned r = (lane >> 2) + (p & 1) * 8;
        unsigned c = (lane & 3) * 2 + (p >> 1) * 8;
        unsigned row = gt * 128 + w * 16 + r;
        unsigned k = kt * 16 + c;
        float2 v = *(const float2*)(W + (size_t)row * KDIM + k);
        hi[p] = (unsigned)f16of(v.x) | ((unsigned)f16of(v.y) << 16);
    }
    size_t fu = ((size_t)(gt * 8 + w) * KT + kt) * 32 + lane;
    ((uint4*)g_WI)[fu] = make_uint4(hi[0], hi[1], hi[2], hi[3]);
}

// ---------------- conv: x [B][S][D] -> B fragments (K=512) ----------------
__global__ void __launch_bounds__(256)
conv_x0_kernel(const float* __restrict__ x)
{
    unsigned idx = blockIdx.x * 256 + threadIdx.x;
    unsigned k4  = idx & 127;
    unsigned n   = (idx >> 7) & 63;
    unsigned s   = idx >> 13;
    float4 v = *(const float4*)(x + ((size_t)n * S_ + s) * D_ + k4 * 4);
    unsigned char* bs = g_xf + (size_t)s * 65536;
    int k = k4 * 4;
    unsigned u0 = (unsigned)f16of(v.x) | ((unsigned)f16of(v.y) << 16);
    unsigned u1 = (unsigned)f16of(v.z) | ((unsigned)f16of(v.w) << 16);
    *(unsigned*)(bs + xf_byte(k, n))     = u0;
    *(unsigned*)(bs + xf_byte(k + 2, n)) = u1;
}

// ---------------- tensor-core layer0 input GEMM with smem B staging ----------------
template<int KT>
__global__ void __launch_bounds__(256)
gemm_mma_kernel(const uint4* __restrict__ WI, const uint4* __restrict__ XF,
                const float* __restrict__ bA, const float* __restrict__ bB,
                float* __restrict__ gx)
{
    extern __shared__ uint4 Bs[];   // [2][2048]: [buf][si*1024 + ktl*128 + q]
    const int tid = threadIdx.x, w = tid >> 5, lane = tid & 31;
    const int gt = blockIdx.x;
    const int s0 = blockIdx.y * 2;
    const int NCHUNK = KT / 8;

    float acc[2][8][4];
#pragma unroll
    for (int si = 0; si < 2; ++si)
#pragma unroll
        for (int nt = 0; nt < 8; ++nt)
#pragma unroll
            for (int q = 0; q < 4; ++q) acc[si][nt][q] = 0.f;

    const uint4* ap = WI + ((size_t)(gt * 8 + w) * KT) * 32 + lane;

    auto issue_chunk = [&](int c, int buf) {
        const uint4* base0 = XF + (size_t)s0 * (KT * 128) + c * 1024;
        const uint4* base1 = base0 + KT * 128;
#pragma unroll
        for (int i = 0; i < 8; ++i) {
            int e = tid + i * 256;
            const uint4* src = (e < 1024) ? (base0 + e) : (base1 + (e - 1024));
            unsigned dst = (unsigned)__cvta_generic_to_shared(Bs + buf * 2048 + e);
            asm volatile("cp.async.cg.shared.global [%0], [%1], 16;" :: "r"(dst), "l"(src));
        }
        asm volatile("cp.async.commit_group;" ::: "memory");
    };

    issue_chunk(0, 0);
    asm volatile("cp.async.wait_group 0;" ::: "memory");
    __syncthreads();

    int buf = 0;
    for (int c = 0; c < NCHUNK; ++c) {
        if (c < NCHUNK - 1) issue_chunk(c + 1, buf ^ 1);

        uint4 As[8];
#pragma unroll
        for (int ktl = 0; ktl < 8; ++ktl) As[ktl] = ap[(size_t)(c * 8 + ktl) * 32];
#pragma unroll
        for (int ktl = 0; ktl < 8; ++ktl) {
            unsigned Ah[4] = {As[ktl].x, As[ktl].y, As[ktl].z, As[ktl].w};
            const uint4* q0 = Bs + buf * 2048 + ktl * 128 + lane;
            const uint4* q1 = q0 + 1024;
#pragma unroll
            for (int ntp = 0; ntp < 4; ++ntp) {
                uint4 B0 = q0[ntp * 32];
                mma16816(acc[0][ntp * 2],     Ah, B0.x, B0.y);
                mma16816(acc[0][ntp * 2 + 1], Ah, B0.z, B0.w);
                uint4 B1 = q1[ntp * 32];
                mma16816(acc[1][ntp * 2],     Ah, B1.x, B1.y);
                mma16816(acc[1][ntp * 2 + 1], Ah, B1.z, B1.w);
            }
        }
        if (c < NCHUNK - 1) {
            asm volatile("cp.async.wait_group 0;" ::: "memory");
            __syncthreads();
            buf ^= 1;
        }
    }

    const int r0 = lane >> 2, c0 = (lane & 3) * 2;
    const int gl = gt * 128 + w * 16 + r0;
    const float biasL = bA[gl] + bB[gl];
    const float biasH = bA[gl + 8] + bB[gl + 8];
#pragma unroll
    for (int si = 0; si < 2; ++si) {
        float* gxs = gx + (size_t)(s0 + si) * G4_ * B_;
#pragma unroll
        for (int nt = 0; nt < 8; ++nt) {
            int c = nt * 8 + c0;
            *(float2*)(gxs + (size_t)gl * B_ + c) =
                make_float2(acc[si][nt][0] + biasL, acc[si][nt][1] + biasL);
            *(float2*)(gxs + (size_t)(gl + 8) * B_ + c) =
                make_float2(acc[si][nt][2] + biasH, acc[si][nt][3] + biasH);
        }
    }
}

// ---------------- weight prep: {Whh0, Whh1, Wih1} -> gate-interleaved A fragments ----------------
__global__ void __launch_bounds__(256)
prep_w_kernel(const float* __restrict__ Whh0, const float* __restrict__ Whh1,
              const float* __restrict__ Wih1)
{
    unsigned idx  = blockIdx.x * 256 + threadIdx.x;   // 3 * 2^19 threads
    unsigned lane = idx & 31;
    unsigned kt   = (idx >> 5) & 7;
    unsigned mt   = (idx >> 8) & 1;
    unsigned w    = (idx >> 9) & 7;
    unsigned cta  = (idx >> 12) & 127;
    unsigned l    = idx >> 19;                        // 0,1,2
    const float* W = (l == 0) ? Whh0 : (l == 1 ? Whh1 : Wih1);

    unsigned hi[4];
#pragma unroll
    for (int p = 0; p < 4; ++p) {
        unsigned r = (lane >> 2) + (p & 1) * 8;
        unsigned c = (lane & 3) * 2 + (p >> 1) * 8;
        unsigned rloc = mt * 16 + r;
        unsigned gr = cta * 32 + rloc;
        unsigned j = gr >> 2, gate = gr & 3;
        unsigned k = w * 128 + kt * 16 + c;
        float2 v = *(const float2*)(W + ((size_t)(gate * H_ + j)) * H_ + k);
        hi[p] = (unsigned)f16of(v.x) | ((unsigned)f16of(v.y) << 16);
    }
    size_t fr = ((((size_t)(l * 128 + cta) * 8 + w) * 2 + mt) * 8 + kt) * 32 + lane;
    ((uint4*)g_WF)[fr] = make_uint4(hi[0], hi[1], hi[2], hi[3]);
}

__global__ void reset_flags_kernel() { g_flags[threadIdx.x] = 0; }

// ---------------- fused 2-layer wavefront recurrence: 257 supersteps ----------------
// Superstep s: phase A computes h1[s]; phase B computes h2[s-1].
// Phase A and phase B's input GEMM share the same B loads (h1frag[(s-1)&1]).
__global__ void __launch_bounds__(256, 1)
fused_recur_kernel(const float* __restrict__ gx,
                   const float* __restrict__ bih1, const float* __restrict__ bhh1,
                   float* __restrict__ hseq2)
{
    extern __shared__ float Rbuf[];

    const int tid  = threadIdx.x;
    const int w    = tid >> 5;
    const int lane = tid & 31;
    const int cta  = blockIdx.x;

    // resident A: layer0 recurrence (slot 0)
    unsigned A0[2][8][4];
    {
        const uint4* wf = (const uint4*)g_WF + (((size_t)cta * 8 + w) * 16) * 32 + lane;
#pragma unroll
        for (int mt = 0; mt < 2; ++mt)
#pragma unroll
            for (int kt = 0; kt < 8; ++kt) {
                uint4 h = wf[(size_t)(mt * 8 + kt) * 32];
                A0[mt][kt][0] = h.x; A0[mt][kt][1] = h.y; A0[mt][kt][2] = h.z; A0[mt][kt][3] = h.w;
            }
    }
    // streamed A: layer1 recurrence (slot 1) and layer1 input (slot 2)
    const uint4* wfR = (const uint4*)g_WF + (((size_t)(128 + cta) * 8 + w) * 16) * 32 + lane;
    const uint4* wfI = (const uint4*)g_WF + (((size_t)(256 + cta) * 8 + w) * 16) * 32 + lane;

    const int n   = tid & 63;
    const int jl0 = tid >> 6;
    float c0[2] = {0.f, 0.f}, c1[2] = {0.f, 0.f};

    float b1v[2][4];
#pragma unroll
    for (int ci = 0; ci < 2; ++ci) {
        int j = cta * 8 + jl0 + ci * 4;
#pragma unroll
        for (int g = 0; g < 4; ++g) b1v[ci][g] = bih1[g * H_ + j] + bhh1[g * H_ + j];
    }

    volatile int* vf = (volatile int*)g_flags;
    const int r0s = lane >> 2, c0s = (lane & 3) * 2;

    for (int s = 0; s <= S_; ++s) {
        // prefetch gx0 (flag-independent); clamp at s==S (result unused there)
        const int sg = (s < S_) ? s : (S_ - 1);
        float pre[2][4];
#pragma unroll
        for (int ci = 0; ci < 2; ++ci) {
            int j = cta * 8 + jl0 + ci * 4;
            const float* gp = gx + ((size_t)sg * G4_ + j) * B_ + n;
            pre[ci][0] = gp[0];
            pre[ci][1] = gp[(size_t)1 * H_ * B_];
            pre[ci][2] = gp[(size_t)2 * H_ * B_];
            pre[ci][3] = gp[(size_t)3 * H_ * B_];
        }

        if (s > 0) {
            if (cta == 0) {
                if (tid < NCTA) { while (vf[tid] < s) {} }
                __syncthreads();
                if (tid == 0) vf[EPOCH] = s;
            } else {
                if (tid == 0) { while (vf[EPOCH] < s) {} }
                __syncthreads();
            }
            __threadfence();
        }

        // ---------------- merged loop: phase A mma + phase B input mma, shared Bv ----------------
        float accBi[2][8][4];
        if (s >= 1) {
            float accA[2][8][4];
#pragma unroll
            for (int mt = 0; mt < 2; ++mt)
#pragma unroll
                for (int nt = 0; nt < 8; ++nt)
#pragma unroll
                    for (int q = 0; q < 4; ++q) { accA[mt][nt][q] = 0.f; accBi[mt][nt][q] = 0.f; }

            const uint4* hb = (const uint4*)g_h1frag + (size_t)((s - 1) & 1) * 8192;
#pragma unroll
            for (int kt = 0; kt < 8; ++kt) {
                uint4 a0v = wfI[(size_t)kt * 32];
                uint4 a1v = wfI[(size_t)(8 + kt) * 32];
                unsigned Ai0[4] = {a0v.x, a0v.y, a0v.z, a0v.w};
                unsigned Ai1[4] = {a1v.x, a1v.y, a1v.z, a1v.w};
                const uint4* kb = hb + ((size_t)(w * 8 + kt) * 4) * 32 + lane;
#pragma unroll
                for (int ntp = 0; ntp < 4; ++ntp) {
                    uint4 Bv = kb[ntp * 32];
                    int nt0 = ntp * 2, nt1 = ntp * 2 + 1;
                    mma16816(accA[0][nt0],  A0[0][kt], Bv.x, Bv.y);
                    mma16816(accA[1][nt0],  A0[1][kt], Bv.x, Bv.y);
                    mma16816(accA[0][nt1],  A0[0][kt], Bv.z, Bv.w);
                    mma16816(accA[1][nt1],  A0[1][kt], Bv.z, Bv.w);
                    mma16816(accBi[0][nt0], Ai0, Bv.x, Bv.y);
                    mma16816(accBi[1][nt0], Ai1, Bv.x, Bv.y);
                    mma16816(accBi[0][nt1], Ai0, Bv.z, Bv.w);
                    mma16816(accBi[1][nt1], Ai1, Bv.z, Bv.w);
                }
            }
#pragma unroll
            for (int mt = 0; mt < 2; ++mt)
#pragma unroll
                for (int nt = 0; nt < 8; ++nt) {
                    float* dst = Rbuf + ((size_t)w * 32 + mt * 16 + r0s) * RSTR + nt * 8 + c0s;
                    *(float2*)dst = make_float2(accA[mt][nt][0], accA[mt][nt][1]);
                    *(float2*)(dst + 8 * RSTR) = make_float2(accA[mt][nt][2], accA[mt][nt][3]);
                }
        }
        __syncthreads();

        // ---------------- epilogue A: h1[s] (harmless garbage at s==S, buffer unread) ----------------
        {
            unsigned char* hfd = g_h1frag + (size_t)(s & 1) * 131072;
#pragma unroll
            for (int ci = 0; ci < 2; ++ci) {
                int jloc = jl0 + ci * 4;
                int j = cta * 8 + jloc;
                float pi = pre[ci][0], pf = pre[ci][1], pg = pre[ci][2], po = pre[ci][3];
                if (s > 0) {
#pragma unroll
                    for (int w8 = 0; w8 < 8; ++w8) {
                        const float* rp = Rbuf + ((size_t)w8 * 32 + jloc * 4) * RSTR + n;
                        pi += rp[0];
                        pf += rp[RSTR];
                        pg += rp[2 * RSTR];
                        po += rp[3 * RSTR];
                    }
                }
                float iv = sigf(pi), fv = sigf(pf), gv = tanhf_(pg), ov = sigf(po);
                c0[ci] = fv * c0[ci] + iv * gv;
                float h = ov * tanhf_(c0[ci]);

                unsigned short hh = f16of(h);
                int ktile = j >> 4, kk = j & 15;
                int nt = n >> 3;
                int flane = (n & 7) * 4 + ((kk & 7) >> 1);
                size_t byte = (((size_t)(ktile * 4 + (nt >> 1)) * 32 + flane) * 16)
                              + (size_t)(nt & 1) * 8 + (kk >> 3) * 4 + (kk & 1) * 2;
                *(unsigned short*)(hfd + byte) = hh;
            }
        }
        __syncthreads();   // Rbuf reuse

        // ---------------- phase B: layer1 recurrence + epilogue, h2[s-1] ----------------
        float h2v[2];
        if (s >= 1) {
            if (s >= 2) {
                const uint4* hb2 = (const uint4*)g_h2frag + (size_t)(s & 1) * 8192;
#pragma unroll
                for (int kt = 0; kt < 8; ++kt) {
                    uint4 a0v = wfR[(size_t)kt * 32];
                    uint4 a1v = wfR[(size_t)(8 + kt) * 32];
                    unsigned Ar0[4] = {a0v.x, a0v.y, a0v.z, a0v.w};
                    unsigned Ar1[4] = {a1v.x, a1v.y, a1v.z, a1v.w};
                    const uint4* kb = hb2 + ((size_t)(w * 8 + kt) * 4) * 32 + lane;
#pragma unroll
                    for (int ntp = 0; ntp < 4; ++ntp) {
                        uint4 Bv = kb[ntp * 32];
                        int nt0 = ntp * 2, nt1 = ntp * 2 + 1;
                        mma16816(accBi[0][nt0], Ar0, Bv.x, Bv.y);
                        mma16816(accBi[1][nt0], Ar1, Bv.x, Bv.y);
                        mma16816(accBi[0][nt1], Ar0, Bv.z, Bv.w);
                        mma16816(accBi[1][nt1], Ar1, Bv.z, Bv.w);
                    }
                }
            }

#pragma unroll
            for (int mt = 0; mt < 2; ++mt)
#pragma unroll
                for (int nt = 0; nt < 8; ++nt) {
                    float* dst = Rbuf + ((size_t)w * 32 + mt * 16 + r0s) * RSTR + nt * 8 + c0s;
                    *(float2*)dst = make_float2(accBi[mt][nt][0], accBi[mt][nt][1]);
                    *(float2*)(dst + 8 * RSTR) = make_float2(accBi[mt][nt][2], accBi[mt][nt][3]);
                }
            __syncthreads();

            unsigned char* hfd2 = g_h2frag + (size_t)((s - 1) & 1) * 131072;
#pragma unroll
            for (int ci = 0; ci < 2; ++ci) {
                int jloc = jl0 + ci * 4;
                int j = cta * 8 + jloc;
                float pi = b1v[ci][0], pf = b1v[ci][1], pg = b1v[ci][2], po = b1v[ci][3];
#pragma unroll
                for (int w8 = 0; w8 < 8; ++w8) {
                    const float* rp = Rbuf + ((size_t)w8 * 32 + jloc * 4) * RSTR + n;
                    pi += rp[0];
                    pf += rp[RSTR];
                    pg += rp[2 * RSTR];
                    po += rp[3 * RSTR];
                }
                float iv = sigf(pi), fv = sigf(pf), gv = tanhf_(pg), ov = sigf(po);
                c1[ci] = fv * c1[ci] + iv * gv;
                float h = ov * tanhf_(c1[ci]);
                h2v[ci] = h;

                unsigned short hh = f16of(h);
                int ktile = j >> 4, kk = j & 15;
                int nt = n >> 3;
                int flane = (n & 7) * 4 + ((kk & 7) >> 1);
                size_t byte = (((size_t)(ktile * 4 + (nt >> 1)) * 32 + flane) * 16)
                              + (size_t)(nt & 1) * 8 + (kk >> 3) * 4 + (kk & 1) * 2;
                *(unsigned short*)(hfd2 + byte) = hh;
            }
        }

        __threadfence();
        __syncthreads();
        if (tid == 0) *((volatile int*)g_flags + cta) = s + 1;

        if (s >= 1) {
#pragma unroll
            for (int ci = 0; ci < 2; ++ci) {
                int j = cta * 8 + jl0 + ci * 4;
                hseq2[((size_t)(s - 1) * H_ + j) * B_ + n] = h2v[ci];
            }
        }
    }
}

// ---------------- fused transpose + sigmoid(relu) ----------------
__global__ void __launch_bounds__(256)
act_out_kernel(const float* __restrict__ h2, float* __restrict__ out)
{
    __shared__ float T[64][68];
    const int s = blockIdx.y, jt = blockIdx.x, t = threadIdx.x;
    {
        int jj0 = (t >> 4) * 4, bq = (t & 15) * 4;
#pragma unroll
        for (int r = 0; r < 4; ++r)
            *(float4*)&T[jj0 + r][bq] =
                *(const float4*)(h2 + ((size_t)s * H_ + jt * 64 + jj0 + r) * B_ + bq);
    }
    __syncthreads();
    {
        int b0 = (t >> 4) * 4, jq = (t & 15) * 4;
#pragma unroll
        for (int i = 0; i < 4; ++i) {
            int b = b0 + i;
            float4 w;
            w.x = actf(T[jq + 0][b]); w.y = actf(T[jq + 1][b]);
            w.z = actf(T[jq + 2][b]); w.w = actf(T[jq + 3][b]);
            *(float4*)(out + (size_t)b * (S_ * H_) + (size_t)s * H_ + jt * 64 + jq) = w;
        }
    }
}

// ---------------- launcher ----------------
extern "C" void kernel_launch(void* const* d_in, const int* in_sizes, int n_in,
                              void* d_out, int out_size)
{
    const float* x    = (const float*)d_in[0];
    const float* Wih0 = (const float*)d_in[1];
    const float* Whh0 = (const float*)d_in[2];
    const float* bih0 = (const float*)d_in[3];
    const float* bhh0 = (const float*)d_in[4];
    const float* Wih1 = (const float*)d_in[5];
    const float* Whh1 = (const float*)d_in[6];
    const float* bih1 = (const float*)d_in[7];
    const float* bhh1 = (const float*)d_in[8];
    float* out = (float*)d_out;

    float *gx, *h2;
    unsigned char* wi;
    unsigned char* xf;
    cudaGetSymbolAddress((void**)&gx, g_gx);
    cudaGetSymbolAddress((void**)&h2, g_h2);
    cudaGetSymbolAddress((void**)&wi, g_WI);
    cudaGetSymbolAddress((void**)&xf, g_xf);

    const int smem_rec  = 8 * 32 * RSTR * (int)sizeof(float);   // 67584
    const int smem_gemm = 2 * 2048 * (int)sizeof(uint4);        // 65536
    cudaFuncSetAttribute(fused_recur_kernel, cudaFuncAttributeMaxDynamicSharedMemorySize, smem_rec);
    cudaFuncSetAttribute(gemm_mma_kernel<32>, cudaFuncAttributeMaxDynamicSharedMemorySize, smem_gemm);

    // one-shot preps
    prep_w_kernel<<<6144, 256>>>(Whh0, Whh1, Wih1);
    prep_wi_kernel<32, D_><<<1024, 256>>>(Wih0);
    conv_x0_kernel<<<8192, 256>>>(x);

    // layer0 input GEMM
    dim3 ggrid(32, 128);
    gemm_mma_kernel<32><<<ggrid, 256, smem_gemm>>>((const uint4*)wi, (const uint4*)xf, bih0, bhh0, gx);

    // fused two-layer recurrence
    reset_flags_kernel<<<1, 256>>>();
    fused_recur_kernel<<<NCTA, 256, smem_rec>>>(gx, bih1, bhh1, h2);

    // epilogue
    dim3 agrid(H_ / 64, S_);
    act_out_kernel<<<agrid, 256>>>(h2, out);
}